// round 11
// baseline (speedup 1.0000x reference)
#include <cuda_runtime.h>
#include <cuda_fp16.h>
#include <cstdint>
#include <cstddef>
#include <cstring>

// Problem constants
#define DIMV   1024
#define HEADS  16
#define DH     64
#define INNERV 1024
#define BATCH  2
#define NSEQ   2048
#define MSEQ   2048
#define RROWS  4096   // BATCH * NSEQ
#define LNEPS  1e-5f
#define LOG2E  1.44269504088896f

// Scratch (device globals: allocation-free per harness rules)
__device__ __half g_xn[RROWS * DIMV];
__device__ __half g_cn[RROWS * DIMV];
__device__ __half g_q [RROWS * INNERV];
__device__ __half g_kv[RROWS * 2 * INNERV];
__device__ __half g_ao[RROWS * INNERV];
__device__ __half g_wq [1024 * 1024];
__device__ __half g_wkv[1024 * 2048];
__device__ __half g_wo [1024 * 1024];

// ---------------------------------------------------------------------------
// Primitives
// ---------------------------------------------------------------------------
__device__ __forceinline__ void mma_f16(float c[4], const uint32_t a[4], const uint32_t b[2]) {
    asm volatile(
        "mma.sync.aligned.m16n8k16.row.col.f32.f16.f16.f32 "
        "{%0,%1,%2,%3}, {%4,%5,%6,%7}, {%8,%9}, {%0,%1,%2,%3};\n"
        : "+f"(c[0]), "+f"(c[1]), "+f"(c[2]), "+f"(c[3])
        : "r"(a[0]), "r"(a[1]), "r"(a[2]), "r"(a[3]), "r"(b[0]), "r"(b[1]));
}

__device__ __forceinline__ void ldsm_x4(uint32_t r[4], uint32_t addr) {
    asm volatile("ldmatrix.sync.aligned.m8n8.x4.shared.b16 {%0,%1,%2,%3}, [%4];"
                 : "=r"(r[0]), "=r"(r[1]), "=r"(r[2]), "=r"(r[3]) : "r"(addr));
}
__device__ __forceinline__ void ldsm_x4_t(uint32_t r[4], uint32_t addr) {
    asm volatile("ldmatrix.sync.aligned.m8n8.x4.trans.shared.b16 {%0,%1,%2,%3}, [%4];"
                 : "=r"(r[0]), "=r"(r[1]), "=r"(r[2]), "=r"(r[3]) : "r"(addr));
}

__device__ __forceinline__ void cp_async16(void* dst_smem, const void* src) {
    unsigned d = (unsigned)__cvta_generic_to_shared(dst_smem);
    asm volatile("cp.async.cg.shared.global [%0], [%1], 16;" :: "r"(d), "l"(src));
}
#define CP_COMMIT() asm volatile("cp.async.commit_group;")
#define CP_WAIT0()  asm volatile("cp.async.wait_group 0;")
#define CP_WAIT1()  asm volatile("cp.async.wait_group 1;")

__device__ __forceinline__ float ex2f(float x) {
    float r;
    asm("ex2.approx.f32 %0, %1;" : "=f"(r) : "f"(x));
    return r;
}
// pack (lo=x, hi=y) with saturate-to-max-finite (no inf on overflow)
__device__ __forceinline__ uint32_t h2u_sat(float x, float y) {
    uint32_t u;
    asm("cvt.rn.satfinite.f16x2.f32 %0, %1, %2;" : "=r"(u) : "f"(y), "f"(x));
    return u;
}

// ---------------------------------------------------------------------------
// Fused pre-pass: LayerNorm (x, ctx) + fp32->fp16 weight convert, one launch
// ---------------------------------------------------------------------------
__global__ __launch_bounds__(256) void prepass_k(
    const float* __restrict__ x,  const float* __restrict__ ctx,
    const float* __restrict__ nw, const float* __restrict__ nb,
    const float* __restrict__ cw, const float* __restrict__ cb,
    __half* __restrict__ xn, __half* __restrict__ cn,
    const float* __restrict__ wq, const float* __restrict__ wkv,
    const float* __restrict__ wo,
    __half* __restrict__ hq, __half* __restrict__ hkv, __half* __restrict__ ho)
{
    int blk = blockIdx.x;
    const int tid = threadIdx.x;

    if (blk >= 2 * RROWS) {
        const size_t i = ((size_t)(blk - 2 * RROWS) * 256 + tid) * 4;
        const float* src; __half* dst; size_t off;
        if (i < (size_t)1024 * 1024) { src = wq; dst = hq; off = i; }
        else if (i < (size_t)(1024 * 1024 + 1024 * 2048)) {
            src = wkv; dst = hkv; off = i - (size_t)1024 * 1024;
        } else { src = wo; dst = ho; off = i - (size_t)(1024 * 1024 + 1024 * 2048); }
        float4 v = *reinterpret_cast<const float4*>(src + off);
        __half2 h0 = __floats2half2_rn(v.x, v.y);
        __half2 h1 = __floats2half2_rn(v.z, v.w);
        uint2 u; memcpy(&u.x, &h0, 4); memcpy(&u.y, &h1, 4);
        *reinterpret_cast<uint2*>(dst + off) = u;
        return;
    }

    int row = blk;
    const float *xp, *w, *b; __half* y;
    if (row < RROWS) { xp = x; w = nw; b = nb; y = xn; }
    else { row -= RROWS; xp = ctx; w = cw; b = cb; y = cn; }

    const float* xr = xp + (size_t)row * DIMV;
    float4 v = reinterpret_cast<const float4*>(xr)[tid];
    float s  = v.x + v.y + v.z + v.w;
    float ss = v.x*v.x + v.y*v.y + v.z*v.z + v.w*v.w;
    #pragma unroll
    for (int o = 16; o > 0; o >>= 1) {
        s  += __shfl_xor_sync(0xffffffffu, s,  o);
        ss += __shfl_xor_sync(0xffffffffu, ss, o);
    }
    __shared__ float sm1[8], sm2[8];
    if ((tid & 31) == 0) { sm1[tid >> 5] = s; sm2[tid >> 5] = ss; }
    __syncthreads();
    float tot = 0.f, tot2 = 0.f;
    #pragma unroll
    for (int i = 0; i < 8; i++) { tot += sm1[i]; tot2 += sm2[i]; }
    const float mu  = tot * (1.0f / DIMV);
    const float var = tot2 * (1.0f / DIMV) - mu * mu;
    const float rs  = rsqrtf(var + LNEPS);
    float4 wv = reinterpret_cast<const float4*>(w)[tid];
    float4 bv = reinterpret_cast<const float4*>(b)[tid];
    __half2 h0 = __floats2half2_rn((v.x - mu) * rs * wv.x + bv.x,
                                   (v.y - mu) * rs * wv.y + bv.y);
    __half2 h1 = __floats2half2_rn((v.z - mu) * rs * wv.z + bv.z,
                                   (v.w - mu) * rs * wv.w + bv.w);
    uint2 u; memcpy(&u.x, &h0, 4); memcpy(&u.y, &h1, 4);
    *reinterpret_cast<uint2*>(y + (size_t)row * DIMV + tid * 4) = u;
}

// ---------------------------------------------------------------------------
// fp16 GEMM: C[128m x 128n tile] = alpha * A[128 x 1024] @ W[1024 x ndim]
// 256 threads, 8 warps (4x2), warp tile 32x64, BK=32.
// 3-stage cp.async ring, wait_group 1 (one tile always in flight).
// ---------------------------------------------------------------------------
#define GROWH 40
#define GTILEH (128 * GROWH)
#define BROWH 136
#define BTILEH (32 * BROWH)
#define GSTAGES 3
#define GT_SMEM_BYTES ((GSTAGES * GTILEH + GSTAGES * BTILEH) * 2)

__device__ __forceinline__ void store2(__half* p, float x, float y) {
    *reinterpret_cast<__half2*>(p) = __floats2half2_rn(x, y);
}
__device__ __forceinline__ void store2(float* p, float x, float y) {
    *reinterpret_cast<float2*>(p) = make_float2(x, y);
}

template<typename OutT>
__device__ __forceinline__ void gemm_body(
    const __half* __restrict__ A, const __half* __restrict__ W,
    OutT* __restrict__ C, int ndim, int bm, int bn, float alpha)
{
    extern __shared__ __align__(16) __half smh[];
    __half* Asm = smh;
    __half* Bsm = smh + GSTAGES * GTILEH;
    const uint32_t sbA = (uint32_t)__cvta_generic_to_shared(Asm);
    const uint32_t sbB = (uint32_t)__cvta_generic_to_shared(Bsm);
    const int tid = threadIdx.x, warp = tid >> 5, lane = tid & 31;
    const int g = lane >> 2, t = lane & 3;
    const int m0 = (warp & 3) * 32, n0 = (warp >> 2) * 64;

    const __half* Ab = A + (size_t)(bm * 128) * 1024;
    const __half* Wb = W + bn * 128;

    float c[2][8][4];
    #pragma unroll
    for (int i = 0; i < 2; i++)
        #pragma unroll
        for (int j = 0; j < 8; j++)
            #pragma unroll
            for (int k = 0; k < 4; k++) c[i][j][k] = 0.f;

    auto prefetch = [&](int kt, int st) {
        __half* as = Asm + st * GTILEH;
        __half* bs = Bsm + st * BTILEH;
        #pragma unroll
        for (int i = 0; i < 2; i++) {
            const int idx = tid + i * 256;
            const int row = idx >> 2, ch = idx & 3;
            cp_async16(as + row * GROWH + ch * 8, Ab + (size_t)row * 1024 + kt * 32 + ch * 8);
        }
        #pragma unroll
        for (int i = 0; i < 2; i++) {
            const int idx = tid + i * 256;
            const int row = idx >> 4, ch = idx & 15;
            cp_async16(bs + row * BROWH + ch * 8, Wb + (size_t)(kt * 32 + row) * ndim + ch * 8);
        }
    };

    const int a_row = (lane & 7) + ((lane >> 3) & 1) * 8;
    const int a_col = (lane >> 4) * 8;
    const int b_row = (lane & 7) + ((lane >> 3) & 1) * 8;
    const int b_col = (lane >> 4) * 8;

    prefetch(0, 0); CP_COMMIT();
    prefetch(1, 1); CP_COMMIT();

    for (int kt = 0; kt < 32; ++kt) {
        const int st = kt % GSTAGES;
        CP_WAIT1();                 // oldest group (this stage) complete
        __syncthreads();
        if (kt + 2 < 32) prefetch(kt + 2, (kt + 2) % GSTAGES);
        CP_COMMIT();                // unconditional: empty groups retire instantly

        const uint32_t as = sbA + st * (GTILEH * 2);
        const uint32_t bs = sbB + st * (BTILEH * 2);
        #pragma unroll
        for (int kk = 0; kk < 2; kk++) {
            const int k0 = kk * 16;
            uint32_t a[2][4];
            #pragma unroll
            for (int mt = 0; mt < 2; mt++)
                ldsm_x4(a[mt], as + ((m0 + mt * 16 + a_row) * GROWH + k0 + a_col) * 2);
            uint32_t bfr[8][2];
            #pragma unroll
            for (int nb = 0; nb < 4; nb++) {
                uint32_t tmp[4];
                ldsm_x4_t(tmp, bs + ((k0 + b_row) * BROWH + n0 + nb * 16 + b_col) * 2);
                bfr[nb*2][0] = tmp[0]; bfr[nb*2][1] = tmp[1];
                bfr[nb*2+1][0] = tmp[2]; bfr[nb*2+1][1] = tmp[3];
            }
            #pragma unroll
            for (int nt = 0; nt < 8; nt++) {
                mma_f16(c[0][nt], a[0], bfr[nt]);
                mma_f16(c[1][nt], a[1], bfr[nt]);
            }
        }
    }

    #pragma unroll
    for (int mt = 0; mt < 2; mt++) {
        #pragma unroll
        for (int nt = 0; nt < 8; nt++) {
            const int row = bm * 128 + m0 + mt * 16 + g;
            const int col = bn * 128 + n0 + nt * 8 + 2 * t;
            store2(C + (size_t)row       * ndim + col, alpha * c[mt][nt][0], alpha * c[mt][nt][1]);
            store2(C + (size_t)(row + 8) * ndim + col, alpha * c[mt][nt][2], alpha * c[mt][nt][3]);
        }
    }
}

__global__ __launch_bounds__(256) void gemm_qkv_k(
    const __half* __restrict__ xn, const __half* __restrict__ wq, __half* __restrict__ qo,
    const __half* __restrict__ cn, const __half* __restrict__ wkv, __half* __restrict__ kvo)
{
    int blk = blockIdx.x;
    if (blk < 256) {
        gemm_body<__half>(xn, wq, qo, 1024, blk >> 3, blk & 7, 0.125f * LOG2E);
    } else {
        blk -= 256;
        gemm_body<__half>(cn, wkv, kvo, 2048, blk >> 4, blk & 15, 1.0f);
    }
}

__global__ __launch_bounds__(256) void gemm_o_k(
    const __half* __restrict__ A, const __half* __restrict__ wo, float* __restrict__ C)
{
    gemm_body<float>(A, wo, C, 1024, blockIdx.x >> 3, blockIdx.x & 7, 1.0f);
}

// ---------------------------------------------------------------------------
// Flash attention, zero-shift log2-domain softmax; 3-stage cp.async ring.
// 128 q-rows/block, 4 warps (32 q-rows each). No running max / rescale.
// ---------------------------------------------------------------------------
#define AROWH 72
#define ATILEH (64 * AROWH)
#define ASTAGES 3
#define AT_SMEM_BYTES (2 * ASTAGES * ATILEH * 2 + ASTAGES * 64 * 4)

__global__ __launch_bounds__(128) void attn_k(
    const __half* __restrict__ q, const __half* __restrict__ kv,
    const int* __restrict__ mask, __half* __restrict__ out)
{
    extern __shared__ __align__(16) __half sha[];
    __half* Ks = sha;                            // [3][64][AROWH]
    __half* Vs = sha + ASTAGES * ATILEH;         // [3][64][AROWH]
    float*  mb = reinterpret_cast<float*>(sha + 2 * ASTAGES * ATILEH);  // [3][64]
    const uint32_t sb = (uint32_t)__cvta_generic_to_shared(sha);

    const int tid = threadIdx.x, warp = tid >> 5, lane = tid & 31;
    const int g = lane >> 2, t = lane & 3;
    const int qt = blockIdx.x, bh = blockIdx.y;
    const int b = bh >> 4, h = bh & 15;

    const __half* kvbase = kv + ((size_t)b * MSEQ) * (2 * INNERV) + h * DH;

    auto prefetch = [&](int kt, int buf) {
        const __half* kb = kvbase + (size_t)(kt * 64) * (2 * INNERV);
        __half* kd = Ks + buf * ATILEH;
        __half* vd = Vs + buf * ATILEH;
        #pragma unroll
        for (int i = 0; i < 4; i++) {
            const int idx = tid + i * 128;
            const int r = idx >> 3, ch = (idx & 7) * 8;
            const __half* src = kb + (size_t)r * (2 * INNERV) + ch;
            cp_async16(kd + r * AROWH + ch, src);
            cp_async16(vd + r * AROWH + ch, src + INNERV);
        }
    };

    prefetch(0, 0); CP_COMMIT();
    prefetch(1, 1); CP_COMMIT();

    // mask scan: is this batch's mask fully true?
    bool lok = true;
    #pragma unroll
    for (int i = 0; i < 4; i++) {
        int4 mv = reinterpret_cast<const int4*>(mask + (size_t)b * MSEQ)[tid + i * 128];
        lok &= (mv.x != 0) & (mv.y != 0) & (mv.z != 0) & (mv.w != 0);
    }
    const int all_true = __syncthreads_and(lok);
    if (all_true) {
        if (tid < 64) { mb[tid] = 0.f; mb[64 + tid] = 0.f; mb[128 + tid] = 0.f; }
    } else if (tid < 64) {
        mb[tid]      = mask[(size_t)b * MSEQ + tid]      ? 0.f : -1e30f;
        mb[64 + tid] = mask[(size_t)b * MSEQ + 64 + tid] ? 0.f : -1e30f;
    }

    // Q fragments for 2 m-tiles (scale*log2e folded at q GEMM)
    uint32_t qf[2][4][4];
    {
        const __half* qb = q + (size_t)(b * NSEQ + qt * 128 + warp * 32) * INNERV + h * DH;
        #pragma unroll
        for (int mt = 0; mt < 2; mt++) {
            const __half* qm = qb + (size_t)(mt * 16) * INNERV;
            #pragma unroll
            for (int kk = 0; kk < 4; kk++) {
                qf[mt][kk][0] = *reinterpret_cast<const uint32_t*>(qm + (size_t)g       * INNERV + kk * 16 + 2 * t);
                qf[mt][kk][1] = *reinterpret_cast<const uint32_t*>(qm + (size_t)(g + 8) * INNERV + kk * 16 + 2 * t);
                qf[mt][kk][2] = *reinterpret_cast<const uint32_t*>(qm + (size_t)g       * INNERV + kk * 16 + 2 * t + 8);
                qf[mt][kk][3] = *reinterpret_cast<const uint32_t*>(qm + (size_t)(g + 8) * INNERV + kk * 16 + 2 * t + 8);
            }
        }
    }

    const int kb_row = (lane & 7) + (lane >> 4) * 8;
    const int kb_col = ((lane >> 3) & 1) * 8;
    const int vb_row = (lane & 7) + ((lane >> 3) & 1) * 8;
    const int vb_col = (lane >> 4) * 8;

    float lst[2][2] = {{0.f, 0.f}, {0.f, 0.f}};
    float o[2][8][4];
    #pragma unroll
    for (int mt = 0; mt < 2; mt++)
        #pragma unroll
        for (int i = 0; i < 8; i++)
            #pragma unroll
            for (int j = 0; j < 4; j++) o[mt][i][j] = 0.f;

    const int NKT = MSEQ / 64;
    for (int kt = 0; kt < NKT; ++kt) {
        const int cur = kt % ASTAGES;
        CP_WAIT1();
        __syncthreads();
        if (kt + 2 < NKT) {
            prefetch(kt + 2, (kt + 2) % ASTAGES);
            if (!all_true && tid < 64)
                mb[((kt + 2) % ASTAGES) * 64 + tid] =
                    mask[(size_t)b * MSEQ + (kt + 2) * 64 + tid] ? 0.f : -1e30f;
        }
        CP_COMMIT();

        const uint32_t Kc = sb + cur * (ATILEH * 2);
        const uint32_t Vc = sb + (ASTAGES + cur) * (ATILEH * 2);
        const float* mbc = mb + cur * 64;

        // S = Q (32x64) @ K^T
        float s[2][8][4];
        #pragma unroll
        for (int mt = 0; mt < 2; mt++)
            #pragma unroll
            for (int i = 0; i < 8; i++)
                #pragma unroll
                for (int j = 0; j < 4; j++) s[mt][i][j] = 0.f;

        #pragma unroll
        for (int kk = 0; kk < 4; kk++) {
            uint32_t kf[8][2];
            #pragma unroll
            for (int nb = 0; nb < 4; nb++) {
                uint32_t tmp[4];
                ldsm_x4(tmp, Kc + ((nb * 16 + kb_row) * AROWH + kk * 16 + kb_col) * 2);
                kf[nb*2][0] = tmp[0]; kf[nb*2][1] = tmp[1];
                kf[nb*2+1][0] = tmp[2]; kf[nb*2+1][1] = tmp[3];
            }
            #pragma unroll
            for (int nt = 0; nt < 8; nt++) {
                mma_f16(s[0][nt], qf[0][kk], kf[nt]);
                mma_f16(s[1][nt], qf[1][kk], kf[nt]);
            }
        }

        // p = exp2(s + bias); accumulate l
        #pragma unroll
        for (int mt = 0; mt < 2; mt++) {
            #pragma unroll
            for (int nt = 0; nt < 8; nt++) {
                const float b0v = mbc[nt * 8 + 2 * t], b1v = mbc[nt * 8 + 2 * t + 1];
                s[mt][nt][0] = ex2f(s[mt][nt][0] + b0v);
                s[mt][nt][1] = ex2f(s[mt][nt][1] + b1v);
                s[mt][nt][2] = ex2f(s[mt][nt][2] + b0v);
                s[mt][nt][3] = ex2f(s[mt][nt][3] + b1v);
                lst[mt][0] += s[mt][nt][0] + s[mt][nt][1];
                lst[mt][1] += s[mt][nt][2] + s[mt][nt][3];
            }
        }

        // O += P @ V
        #pragma unroll
        for (int kk = 0; kk < 4; kk++) {
            uint32_t pa[2][4];
            #pragma unroll
            for (int mt = 0; mt < 2; mt++) {
                pa[mt][0] = h2u_sat(s[mt][2*kk][0],   s[mt][2*kk][1]);
                pa[mt][1] = h2u_sat(s[mt][2*kk][2],   s[mt][2*kk][3]);
                pa[mt][2] = h2u_sat(s[mt][2*kk+1][0], s[mt][2*kk+1][1]);
                pa[mt][3] = h2u_sat(s[mt][2*kk+1][2], s[mt][2*kk+1][3]);
            }
            uint32_t vf[8][2];
            #pragma unroll
            for (int nb = 0; nb < 4; nb++) {
                uint32_t tmp[4];
                ldsm_x4_t(tmp, Vc + ((kk * 16 + vb_row) * AROWH + nb * 16 + vb_col) * 2);
                vf[nb*2][0] = tmp[0]; vf[nb*2][1] = tmp[1];
                vf[nb*2+1][0] = tmp[2]; vf[nb*2+1][1] = tmp[3];
            }
            #pragma unroll
            for (int nt = 0; nt < 8; nt++) {
                mma_f16(o[0][nt], pa[0], vf[nt]);
                mma_f16(o[1][nt], pa[1], vf[nt]);
            }
        }
    }

    // final lane reduction of row sums
    #pragma unroll
    for (int mt = 0; mt < 2; mt++) {
        #pragma unroll
        for (int j = 0; j < 2; j++) {
            lst[mt][j] += __shfl_xor_sync(0xffffffffu, lst[mt][j], 1);
            lst[mt][j] += __shfl_xor_sync(0xffffffffu, lst[mt][j], 2);
        }
    }

    #pragma unroll
    for (int mt = 0; mt < 2; mt++) {
        const float inv0 = 1.f / lst[mt][0], inv1 = 1.f / lst[mt][1];
        const int row0 = b * NSEQ + qt * 128 + warp * 32 + mt * 16 + g;
        #pragma unroll
        for (int nt = 0; nt < 8; nt++) {
            const int col = h * DH + nt * 8 + 2 * t;
            *reinterpret_cast<__half2*>(&out[(size_t)row0 * INNERV + col]) =
                __floats2half2_rn(o[mt][nt][0] * inv0, o[mt][nt][1] * inv0);
            *reinterpret_cast<__half2*>(&out[(size_t)(row0 + 8) * INNERV + col]) =
                __floats2half2_rn(o[mt][nt][2] * inv1, o[mt][nt][3] * inv1);
        }
    }
}

// ---------------------------------------------------------------------------
// Launch
// ---------------------------------------------------------------------------
extern "C" void kernel_launch(void* const* d_in, const int* in_sizes, int n_in,
                              void* d_out, int out_size)
{
    (void)in_sizes; (void)n_in; (void)out_size;
    const float* x    = (const float*)d_in[0];
    const float* ctx  = (const float*)d_in[1];
    const float* nw   = (const float*)d_in[2];
    const float* nb   = (const float*)d_in[3];
    const float* cw   = (const float*)d_in[4];
    const float* cb   = (const float*)d_in[5];
    const float* Wq   = (const float*)d_in[6];
    const float* Wkv  = (const float*)d_in[7];
    const float* Wo   = (const float*)d_in[8];
    const int*   mask = (const int*)d_in[9];
    float* out = (float*)d_out;

    __half *xn, *cn, *qb, *kvb, *ao, *hwq, *hwkv, *hwo;
    cudaGetSymbolAddress((void**)&xn,   g_xn);
    cudaGetSymbolAddress((void**)&cn,   g_cn);
    cudaGetSymbolAddress((void**)&qb,   g_q);
    cudaGetSymbolAddress((void**)&kvb,  g_kv);
    cudaGetSymbolAddress((void**)&ao,   g_ao);
    cudaGetSymbolAddress((void**)&hwq,  g_wq);
    cudaGetSymbolAddress((void**)&hwkv, g_wkv);
    cudaGetSymbolAddress((void**)&hwo,  g_wo);

    // fused LN + weight convert
    prepass_k<<<2 * RROWS + 4096, 256>>>(x, ctx, nw, nb, cw, cb, xn, cn,
                                         Wq, Wkv, Wo, hwq, hwkv, hwo);

    cudaFuncSetAttribute(gemm_qkv_k, cudaFuncAttributeMaxDynamicSharedMemorySize, GT_SMEM_BYTES);
    cudaFuncSetAttribute(gemm_o_k,   cudaFuncAttributeMaxDynamicSharedMemorySize, GT_SMEM_BYTES);

    gemm_qkv_k<<<768, 256, GT_SMEM_BYTES>>>(xn, hwq, qb, cn, hwkv, kvb);

    cudaFuncSetAttribute(attn_k, cudaFuncAttributeMaxDynamicSharedMemorySize, AT_SMEM_BYTES);
    attn_k<<<dim3(NSEQ / 128, BATCH * HEADS), 128, AT_SMEM_BYTES>>>(qb, kvb, mask, ao);

    gemm_o_k<<<256, 256, GT_SMEM_BYTES>>>(ao, hwo, out);
}

// round 12
// speedup vs baseline: 1.0282x; 1.0282x over previous
#include <cuda_runtime.h>
#include <cuda_fp16.h>
#include <cstdint>
#include <cstddef>
#include <cstring>

// Problem constants
#define DIMV   1024
#define HEADS  16
#define DH     64
#define INNERV 1024
#define BATCH  2
#define NSEQ   2048
#define MSEQ   2048
#define RROWS  4096   // BATCH * NSEQ
#define LNEPS  1e-5f
#define LOG2E  1.44269504088896f

// Scratch (device globals: allocation-free per harness rules)
__device__ __half g_xn[RROWS * DIMV];
__device__ __half g_cn[RROWS * DIMV];
__device__ __half g_q [RROWS * INNERV];
__device__ __half g_kv[RROWS * 2 * INNERV];
__device__ __half g_ao[RROWS * INNERV];
__device__ __half g_wq [1024 * 1024];
__device__ __half g_wkv[1024 * 2048];
__device__ __half g_wo [1024 * 1024];

// ---------------------------------------------------------------------------
// Primitives
// ---------------------------------------------------------------------------
__device__ __forceinline__ void mma_f16(float c[4], const uint32_t a[4], const uint32_t b[2]) {
    asm volatile(
        "mma.sync.aligned.m16n8k16.row.col.f32.f16.f16.f32 "
        "{%0,%1,%2,%3}, {%4,%5,%6,%7}, {%8,%9}, {%0,%1,%2,%3};\n"
        : "+f"(c[0]), "+f"(c[1]), "+f"(c[2]), "+f"(c[3])
        : "r"(a[0]), "r"(a[1]), "r"(a[2]), "r"(a[3]), "r"(b[0]), "r"(b[1]));
}

__device__ __forceinline__ void ldsm_x4(uint32_t r[4], uint32_t addr) {
    asm volatile("ldmatrix.sync.aligned.m8n8.x4.shared.b16 {%0,%1,%2,%3}, [%4];"
                 : "=r"(r[0]), "=r"(r[1]), "=r"(r[2]), "=r"(r[3]) : "r"(addr));
}
__device__ __forceinline__ void ldsm_x4_t(uint32_t r[4], uint32_t addr) {
    asm volatile("ldmatrix.sync.aligned.m8n8.x4.trans.shared.b16 {%0,%1,%2,%3}, [%4];"
                 : "=r"(r[0]), "=r"(r[1]), "=r"(r[2]), "=r"(r[3]) : "r"(addr));
}

__device__ __forceinline__ void cp_async16(void* dst_smem, const void* src) {
    unsigned d = (unsigned)__cvta_generic_to_shared(dst_smem);
    asm volatile("cp.async.cg.shared.global [%0], [%1], 16;" :: "r"(d), "l"(src));
}
#define CP_COMMIT() asm volatile("cp.async.commit_group;")
#define CP_WAIT1()  asm volatile("cp.async.wait_group 1;")

__device__ __forceinline__ float ex2f(float x) {
    float r;
    asm("ex2.approx.f32 %0, %1;" : "=f"(r) : "f"(x));
    return r;
}
// pack (lo=x, hi=y) with saturate-to-max-finite (no inf on overflow)
__device__ __forceinline__ uint32_t h2u_sat(float x, float y) {
    uint32_t u;
    asm("cvt.rn.satfinite.f16x2.f32 %0, %1, %2;" : "=r"(u) : "f"(y), "f"(x));
    return u;
}

// ---------------------------------------------------------------------------
// Fused pre-pass: LayerNorm (x, ctx) + fp32->fp16 weight convert, one launch
// ---------------------------------------------------------------------------
__global__ __launch_bounds__(256) void prepass_k(
    const float* __restrict__ x,  const float* __restrict__ ctx,
    const float* __restrict__ nw, const float* __restrict__ nb,
    const float* __restrict__ cw, const float* __restrict__ cb,
    __half* __restrict__ xn, __half* __restrict__ cn,
    const float* __restrict__ wq, const float* __restrict__ wkv,
    const float* __restrict__ wo,
    __half* __restrict__ hq, __half* __restrict__ hkv, __half* __restrict__ ho)
{
    int blk = blockIdx.x;
    const int tid = threadIdx.x;

    if (blk >= 2 * RROWS) {
        const size_t i = ((size_t)(blk - 2 * RROWS) * 256 + tid) * 4;
        const float* src; __half* dst; size_t off;
        if (i < (size_t)1024 * 1024) { src = wq; dst = hq; off = i; }
        else if (i < (size_t)(1024 * 1024 + 1024 * 2048)) {
            src = wkv; dst = hkv; off = i - (size_t)1024 * 1024;
        } else { src = wo; dst = ho; off = i - (size_t)(1024 * 1024 + 1024 * 2048); }
        float4 v = *reinterpret_cast<const float4*>(src + off);
        __half2 h0 = __floats2half2_rn(v.x, v.y);
        __half2 h1 = __floats2half2_rn(v.z, v.w);
        uint2 u; memcpy(&u.x, &h0, 4); memcpy(&u.y, &h1, 4);
        *reinterpret_cast<uint2*>(dst + off) = u;
        return;
    }

    int row = blk;
    const float *xp, *w, *b; __half* y;
    if (row < RROWS) { xp = x; w = nw; b = nb; y = xn; }
    else { row -= RROWS; xp = ctx; w = cw; b = cb; y = cn; }

    const float* xr = xp + (size_t)row * DIMV;
    float4 v = reinterpret_cast<const float4*>(xr)[tid];
    float s  = v.x + v.y + v.z + v.w;
    float ss = v.x*v.x + v.y*v.y + v.z*v.z + v.w*v.w;
    #pragma unroll
    for (int o = 16; o > 0; o >>= 1) {
        s  += __shfl_xor_sync(0xffffffffu, s,  o);
        ss += __shfl_xor_sync(0xffffffffu, ss, o);
    }
    __shared__ float sm1[8], sm2[8];
    if ((tid & 31) == 0) { sm1[tid >> 5] = s; sm2[tid >> 5] = ss; }
    __syncthreads();
    float tot = 0.f, tot2 = 0.f;
    #pragma unroll
    for (int i = 0; i < 8; i++) { tot += sm1[i]; tot2 += sm2[i]; }
    const float mu  = tot * (1.0f / DIMV);
    const float var = tot2 * (1.0f / DIMV) - mu * mu;
    const float rs  = rsqrtf(var + LNEPS);
    float4 wv = reinterpret_cast<const float4*>(w)[tid];
    float4 bv = reinterpret_cast<const float4*>(b)[tid];
    __half2 h0 = __floats2half2_rn((v.x - mu) * rs * wv.x + bv.x,
                                   (v.y - mu) * rs * wv.y + bv.y);
    __half2 h1 = __floats2half2_rn((v.z - mu) * rs * wv.z + bv.z,
                                   (v.w - mu) * rs * wv.w + bv.w);
    uint2 u; memcpy(&u.x, &h0, 4); memcpy(&u.y, &h1, 4);
    *reinterpret_cast<uint2*>(y + (size_t)row * DIMV + tid * 4) = u;
}

// ---------------------------------------------------------------------------
// fp16 GEMM: C[128m x 128n tile] = alpha * A[128 x 1024] @ W[1024 x ndim]
// 128 threads, 4 warps (2x2), warp tile 64x64, BK=32.
// 3-stage cp.async ring, wait_group 1. 128 B smem traffic per MMA.
// ---------------------------------------------------------------------------
#define GROWH 40
#define GTILEH (128 * GROWH)
#define BROWH 136
#define BTILEH (32 * BROWH)
#define GSTAGES 3
#define GT_SMEM_BYTES ((GSTAGES * GTILEH + GSTAGES * BTILEH) * 2)

__device__ __forceinline__ void store2(__half* p, float x, float y) {
    *reinterpret_cast<__half2*>(p) = __floats2half2_rn(x, y);
}
__device__ __forceinline__ void store2(float* p, float x, float y) {
    *reinterpret_cast<float2*>(p) = make_float2(x, y);
}

template<typename OutT>
__device__ __forceinline__ void gemm_body(
    const __half* __restrict__ A, const __half* __restrict__ W,
    OutT* __restrict__ C, int ndim, int bm, int bn, float alpha)
{
    extern __shared__ __align__(16) __half smh[];
    __half* Asm = smh;
    __half* Bsm = smh + GSTAGES * GTILEH;
    const uint32_t sbA = (uint32_t)__cvta_generic_to_shared(Asm);
    const uint32_t sbB = (uint32_t)__cvta_generic_to_shared(Bsm);
    const int tid = threadIdx.x, warp = tid >> 5, lane = tid & 31;
    const int g = lane >> 2, t = lane & 3;
    const int m0 = (warp & 1) * 64, n0 = (warp >> 1) * 64;

    const __half* Ab = A + (size_t)(bm * 128) * 1024;
    const __half* Wb = W + bn * 128;

    float c[4][8][4];
    #pragma unroll
    for (int i = 0; i < 4; i++)
        #pragma unroll
        for (int j = 0; j < 8; j++)
            #pragma unroll
            for (int k = 0; k < 4; k++) c[i][j][k] = 0.f;

    auto prefetch = [&](int kt, int st) {
        __half* as = Asm + st * GTILEH;
        __half* bs = Bsm + st * BTILEH;
        #pragma unroll
        for (int i = 0; i < 4; i++) {
            const int idx = tid + i * 128;          // 0..511
            const int row = idx >> 2, ch = idx & 3;
            cp_async16(as + row * GROWH + ch * 8, Ab + (size_t)row * 1024 + kt * 32 + ch * 8);
        }
        #pragma unroll
        for (int i = 0; i < 4; i++) {
            const int idx = tid + i * 128;          // 0..511
            const int row = idx >> 4, ch = idx & 15;
            cp_async16(bs + row * BROWH + ch * 8, Wb + (size_t)(kt * 32 + row) * ndim + ch * 8);
        }
    };

    const int a_row = (lane & 7) + ((lane >> 3) & 1) * 8;
    const int a_col = (lane >> 4) * 8;
    const int b_row = (lane & 7) + ((lane >> 3) & 1) * 8;
    const int b_col = (lane >> 4) * 8;

    prefetch(0, 0); CP_COMMIT();
    prefetch(1, 1); CP_COMMIT();

    for (int kt = 0; kt < 32; ++kt) {
        const int st = kt % GSTAGES;
        CP_WAIT1();
        __syncthreads();
        if (kt + 2 < 32) prefetch(kt + 2, (kt + 2) % GSTAGES);
        CP_COMMIT();

        const uint32_t as = sbA + st * (GTILEH * 2);
        const uint32_t bs = sbB + st * (BTILEH * 2);
        #pragma unroll
        for (int kk = 0; kk < 2; kk++) {
            const int k0 = kk * 16;
            uint32_t a[4][4];
            #pragma unroll
            for (int mt = 0; mt < 4; mt++)
                ldsm_x4(a[mt], as + ((m0 + mt * 16 + a_row) * GROWH + k0 + a_col) * 2);
            uint32_t bfr[8][2];
            #pragma unroll
            for (int nb = 0; nb < 4; nb++) {
                uint32_t tmp[4];
                ldsm_x4_t(tmp, bs + ((k0 + b_row) * BROWH + n0 + nb * 16 + b_col) * 2);
                bfr[nb*2][0] = tmp[0]; bfr[nb*2][1] = tmp[1];
                bfr[nb*2+1][0] = tmp[2]; bfr[nb*2+1][1] = tmp[3];
            }
            #pragma unroll
            for (int mt = 0; mt < 4; mt++)
                #pragma unroll
                for (int nt = 0; nt < 8; nt++)
                    mma_f16(c[mt][nt], a[mt], bfr[nt]);
        }
    }

    #pragma unroll
    for (int mt = 0; mt < 4; mt++) {
        #pragma unroll
        for (int nt = 0; nt < 8; nt++) {
            const int row = bm * 128 + m0 + mt * 16 + g;
            const int col = bn * 128 + n0 + nt * 8 + 2 * t;
            store2(C + (size_t)row       * ndim + col, alpha * c[mt][nt][0], alpha * c[mt][nt][1]);
            store2(C + (size_t)(row + 8) * ndim + col, alpha * c[mt][nt][2], alpha * c[mt][nt][3]);
        }
    }
}

__global__ __launch_bounds__(128) void gemm_qkv_k(
    const __half* __restrict__ xn, const __half* __restrict__ wq, __half* __restrict__ qo,
    const __half* __restrict__ cn, const __half* __restrict__ wkv, __half* __restrict__ kvo)
{
    int blk = blockIdx.x;
    if (blk < 256) {
        gemm_body<__half>(xn, wq, qo, 1024, blk >> 3, blk & 7, 0.125f * LOG2E);
    } else {
        blk -= 256;
        gemm_body<__half>(cn, wkv, kvo, 2048, blk >> 4, blk & 15, 1.0f);
    }
}

__global__ __launch_bounds__(128) void gemm_o_k(
    const __half* __restrict__ A, const __half* __restrict__ wo, float* __restrict__ C)
{
    gemm_body<float>(A, wo, C, 1024, blockIdx.x >> 3, blockIdx.x & 7, 1.0f);
}

// ---------------------------------------------------------------------------
// Flash attention, zero-shift log2-domain softmax; 3-stage cp.async ring.
// 128 q-rows/block, 4 warps (32 q-rows each). No running max / rescale.
// ---------------------------------------------------------------------------
#define AROWH 72
#define ATILEH (64 * AROWH)
#define ASTAGES 3
#define AT_SMEM_BYTES (2 * ASTAGES * ATILEH * 2 + ASTAGES * 64 * 4)

__global__ __launch_bounds__(128) void attn_k(
    const __half* __restrict__ q, const __half* __restrict__ kv,
    const int* __restrict__ mask, __half* __restrict__ out)
{
    extern __shared__ __align__(16) __half sha[];
    __half* Ks = sha;                            // [3][64][AROWH]
    __half* Vs = sha + ASTAGES * ATILEH;         // [3][64][AROWH]
    float*  mb = reinterpret_cast<float*>(sha + 2 * ASTAGES * ATILEH);  // [3][64]
    const uint32_t sb = (uint32_t)__cvta_generic_to_shared(sha);

    const int tid = threadIdx.x, warp = tid >> 5, lane = tid & 31;
    const int g = lane >> 2, t = lane & 3;
    const int qt = blockIdx.x, bh = blockIdx.y;
    const int b = bh >> 4, h = bh & 15;

    const __half* kvbase = kv + ((size_t)b * MSEQ) * (2 * INNERV) + h * DH;

    auto prefetch = [&](int kt, int buf) {
        const __half* kb = kvbase + (size_t)(kt * 64) * (2 * INNERV);
        __half* kd = Ks + buf * ATILEH;
        __half* vd = Vs + buf * ATILEH;
        #pragma unroll
        for (int i = 0; i < 4; i++) {
            const int idx = tid + i * 128;
            const int r = idx >> 3, ch = (idx & 7) * 8;
            const __half* src = kb + (size_t)r * (2 * INNERV) + ch;
            cp_async16(kd + r * AROWH + ch, src);
            cp_async16(vd + r * AROWH + ch, src + INNERV);
        }
    };

    prefetch(0, 0); CP_COMMIT();
    prefetch(1, 1); CP_COMMIT();

    // mask scan: is this batch's mask fully true?
    bool lok = true;
    #pragma unroll
    for (int i = 0; i < 4; i++) {
        int4 mv = reinterpret_cast<const int4*>(mask + (size_t)b * MSEQ)[tid + i * 128];
        lok &= (mv.x != 0) & (mv.y != 0) & (mv.z != 0) & (mv.w != 0);
    }
    const int all_true = __syncthreads_and(lok);
    if (all_true) {
        if (tid < 64) { mb[tid] = 0.f; mb[64 + tid] = 0.f; mb[128 + tid] = 0.f; }
    } else if (tid < 64) {
        mb[tid]      = mask[(size_t)b * MSEQ + tid]      ? 0.f : -1e30f;
        mb[64 + tid] = mask[(size_t)b * MSEQ + 64 + tid] ? 0.f : -1e30f;
    }

    // Q fragments for 2 m-tiles (scale*log2e folded at q GEMM)
    uint32_t qf[2][4][4];
    {
        const __half* qb = q + (size_t)(b * NSEQ + qt * 128 + warp * 32) * INNERV + h * DH;
        #pragma unroll
        for (int mt = 0; mt < 2; mt++) {
            const __half* qm = qb + (size_t)(mt * 16) * INNERV;
            #pragma unroll
            for (int kk = 0; kk < 4; kk++) {
                qf[mt][kk][0] = *reinterpret_cast<const uint32_t*>(qm + (size_t)g       * INNERV + kk * 16 + 2 * t);
                qf[mt][kk][1] = *reinterpret_cast<const uint32_t*>(qm + (size_t)(g + 8) * INNERV + kk * 16 + 2 * t);
                qf[mt][kk][2] = *reinterpret_cast<const uint32_t*>(qm + (size_t)g       * INNERV + kk * 16 + 2 * t + 8);
                qf[mt][kk][3] = *reinterpret_cast<const uint32_t*>(qm + (size_t)(g + 8) * INNERV + kk * 16 + 2 * t + 8);
            }
        }
    }

    const int kb_row = (lane & 7) + (lane >> 4) * 8;
    const int kb_col = ((lane >> 3) & 1) * 8;
    const int vb_row = (lane & 7) + ((lane >> 3) & 1) * 8;
    const int vb_col = (lane >> 4) * 8;

    float lst[2][2] = {{0.f, 0.f}, {0.f, 0.f}};
    float o[2][8][4];
    #pragma unroll
    for (int mt = 0; mt < 2; mt++)
        #pragma unroll
        for (int i = 0; i < 8; i++)
            #pragma unroll
            for (int j = 0; j < 4; j++) o[mt][i][j] = 0.f;

    const int NKT = MSEQ / 64;
    for (int kt = 0; kt < NKT; ++kt) {
        const int cur = kt % ASTAGES;
        CP_WAIT1();
        __syncthreads();
        if (kt + 2 < NKT) {
            prefetch(kt + 2, (kt + 2) % ASTAGES);
            if (!all_true && tid < 64)
                mb[((kt + 2) % ASTAGES) * 64 + tid] =
                    mask[(size_t)b * MSEQ + (kt + 2) * 64 + tid] ? 0.f : -1e30f;
        }
        CP_COMMIT();

        const uint32_t Kc = sb + cur * (ATILEH * 2);
        const uint32_t Vc = sb + (ASTAGES + cur) * (ATILEH * 2);
        const float* mbc = mb + cur * 64;

        // S = Q (32x64) @ K^T
        float s[2][8][4];
        #pragma unroll
        for (int mt = 0; mt < 2; mt++)
            #pragma unroll
            for (int i = 0; i < 8; i++)
                #pragma unroll
                for (int j = 0; j < 4; j++) s[mt][i][j] = 0.f;

        #pragma unroll
        for (int kk = 0; kk < 4; kk++) {
            uint32_t kf[8][2];
            #pragma unroll
            for (int nb = 0; nb < 4; nb++) {
                uint32_t tmp[4];
                ldsm_x4(tmp, Kc + ((nb * 16 + kb_row) * AROWH + kk * 16 + kb_col) * 2);
                kf[nb*2][0] = tmp[0]; kf[nb*2][1] = tmp[1];
                kf[nb*2+1][0] = tmp[2]; kf[nb*2+1][1] = tmp[3];
            }
            #pragma unroll
            for (int nt = 0; nt < 8; nt++) {
                mma_f16(s[0][nt], qf[0][kk], kf[nt]);
                mma_f16(s[1][nt], qf[1][kk], kf[nt]);
            }
        }

        // p = exp2(s + bias); accumulate l
        #pragma unroll
        for (int mt = 0; mt < 2; mt++) {
            #pragma unroll
            for (int nt = 0; nt < 8; nt++) {
                const float b0v = mbc[nt * 8 + 2 * t], b1v = mbc[nt * 8 + 2 * t + 1];
                s[mt][nt][0] = ex2f(s[mt][nt][0] + b0v);
                s[mt][nt][1] = ex2f(s[mt][nt][1] + b1v);
                s[mt][nt][2] = ex2f(s[mt][nt][2] + b0v);
                s[mt][nt][3] = ex2f(s[mt][nt][3] + b1v);
                lst[mt][0] += s[mt][nt][0] + s[mt][nt][1];
                lst[mt][1] += s[mt][nt][2] + s[mt][nt][3];
            }
        }

        // O += P @ V
        #pragma unroll
        for (int kk = 0; kk < 4; kk++) {
            uint32_t pa[2][4];
            #pragma unroll
            for (int mt = 0; mt < 2; mt++) {
                pa[mt][0] = h2u_sat(s[mt][2*kk][0],   s[mt][2*kk][1]);
                pa[mt][1] = h2u_sat(s[mt][2*kk][2],   s[mt][2*kk][3]);
                pa[mt][2] = h2u_sat(s[mt][2*kk+1][0], s[mt][2*kk+1][1]);
                pa[mt][3] = h2u_sat(s[mt][2*kk+1][2], s[mt][2*kk+1][3]);
            }
            uint32_t vf[8][2];
            #pragma unroll
            for (int nb = 0; nb < 4; nb++) {
                uint32_t tmp[4];
                ldsm_x4_t(tmp, Vc + ((kk * 16 + vb_row) * AROWH + nb * 16 + vb_col) * 2);
                vf[nb*2][0] = tmp[0]; vf[nb*2][1] = tmp[1];
                vf[nb*2+1][0] = tmp[2]; vf[nb*2+1][1] = tmp[3];
            }
            #pragma unroll
            for (int nt = 0; nt < 8; nt++) {
                mma_f16(o[0][nt], pa[0], vf[nt]);
                mma_f16(o[1][nt], pa[1], vf[nt]);
            }
        }
    }

    // final lane reduction of row sums
    #pragma unroll
    for (int mt = 0; mt < 2; mt++) {
        #pragma unroll
        for (int j = 0; j < 2; j++) {
            lst[mt][j] += __shfl_xor_sync(0xffffffffu, lst[mt][j], 1);
            lst[mt][j] += __shfl_xor_sync(0xffffffffu, lst[mt][j], 2);
        }
    }

    #pragma unroll
    for (int mt = 0; mt < 2; mt++) {
        const float inv0 = 1.f / lst[mt][0], inv1 = 1.f / lst[mt][1];
        const int row0 = b * NSEQ + qt * 128 + warp * 32 + mt * 16 + g;
        #pragma unroll
        for (int nt = 0; nt < 8; nt++) {
            const int col = h * DH + nt * 8 + 2 * t;
            *reinterpret_cast<__half2*>(&out[(size_t)row0 * INNERV + col]) =
                __floats2half2_rn(o[mt][nt][0] * inv0, o[mt][nt][1] * inv0);
            *reinterpret_cast<__half2*>(&out[(size_t)(row0 + 8) * INNERV + col]) =
                __floats2half2_rn(o[mt][nt][2] * inv1, o[mt][nt][3] * inv1);
        }
    }
}

// ---------------------------------------------------------------------------
// Launch
// ---------------------------------------------------------------------------
extern "C" void kernel_launch(void* const* d_in, const int* in_sizes, int n_in,
                              void* d_out, int out_size)
{
    (void)in_sizes; (void)n_in; (void)out_size;
    const float* x    = (const float*)d_in[0];
    const float* ctx  = (const float*)d_in[1];
    const float* nw   = (const float*)d_in[2];
    const float* nb   = (const float*)d_in[3];
    const float* cw   = (const float*)d_in[4];
    const float* cb   = (const float*)d_in[5];
    const float* Wq   = (const float*)d_in[6];
    const float* Wkv  = (const float*)d_in[7];
    const float* Wo   = (const float*)d_in[8];
    const int*   mask = (const int*)d_in[9];
    float* out = (float*)d_out;

    __half *xn, *cn, *qb, *kvb, *ao, *hwq, *hwkv, *hwo;
    cudaGetSymbolAddress((void**)&xn,   g_xn);
    cudaGetSymbolAddress((void**)&cn,   g_cn);
    cudaGetSymbolAddress((void**)&qb,   g_q);
    cudaGetSymbolAddress((void**)&kvb,  g_kv);
    cudaGetSymbolAddress((void**)&ao,   g_ao);
    cudaGetSymbolAddress((void**)&hwq,  g_wq);
    cudaGetSymbolAddress((void**)&hwkv, g_wkv);
    cudaGetSymbolAddress((void**)&hwo,  g_wo);

    // fused LN + weight convert
    prepass_k<<<2 * RROWS + 4096, 256>>>(x, ctx, nw, nb, cw, cb, xn, cn,
                                         Wq, Wkv, Wo, hwq, hwkv, hwo);

    cudaFuncSetAttribute(gemm_qkv_k, cudaFuncAttributeMaxDynamicSharedMemorySize, GT_SMEM_BYTES);
    cudaFuncSetAttribute(gemm_o_k,   cudaFuncAttributeMaxDynamicSharedMemorySize, GT_SMEM_BYTES);

    gemm_qkv_k<<<768, 128, GT_SMEM_BYTES>>>(xn, hwq, qb, cn, hwkv, kvb);

    cudaFuncSetAttribute(attn_k, cudaFuncAttributeMaxDynamicSharedMemorySize, AT_SMEM_BYTES);
    attn_k<<<dim3(NSEQ / 128, BATCH * HEADS), 128, AT_SMEM_BYTES>>>(qb, kvb, mask, ao);

    gemm_o_k<<<256, 128, GT_SMEM_BYTES>>>(ao, hwo, out);
}

// round 14
// speedup vs baseline: 1.0621x; 1.0330x over previous
#include <cuda_runtime.h>
#include <cuda_fp16.h>
#include <cstdint>
#include <cstddef>
#include <cstring>

// Problem constants
#define DIMV   1024
#define HEADS  16
#define DH     64
#define INNERV 1024
#define BATCH  2
#define NSEQ   2048
#define MSEQ   2048
#define RROWS  4096   // BATCH * NSEQ
#define LNEPS  1e-5f
#define LOG2E  1.44269504088896f

// Scratch (device globals: allocation-free per harness rules)
__device__ __half g_xn[RROWS * DIMV];
__device__ __half g_cn[RROWS * DIMV];
__device__ __half g_q [RROWS * INNERV];
__device__ __half g_kv[RROWS * 2 * INNERV];
__device__ __half g_ao[RROWS * INNERV];
__device__ __half g_wq [1024 * 1024];
__device__ __half g_wkv[1024 * 2048];
__device__ __half g_wo [1024 * 1024];

// ---------------------------------------------------------------------------
// Primitives
// ---------------------------------------------------------------------------
__device__ __forceinline__ void mma_f16(float c[4], const uint32_t a[4], const uint32_t b[2]) {
    asm volatile(
        "mma.sync.aligned.m16n8k16.row.col.f32.f16.f16.f32 "
        "{%0,%1,%2,%3}, {%4,%5,%6,%7}, {%8,%9}, {%0,%1,%2,%3};\n"
        : "+f"(c[0]), "+f"(c[1]), "+f"(c[2]), "+f"(c[3])
        : "r"(a[0]), "r"(a[1]), "r"(a[2]), "r"(a[3]), "r"(b[0]), "r"(b[1]));
}

__device__ __forceinline__ void ldsm_x4(uint32_t r[4], uint32_t addr) {
    asm volatile("ldmatrix.sync.aligned.m8n8.x4.shared.b16 {%0,%1,%2,%3}, [%4];"
                 : "=r"(r[0]), "=r"(r[1]), "=r"(r[2]), "=r"(r[3]) : "r"(addr));
}
__device__ __forceinline__ void ldsm_x4_t(uint32_t r[4], uint32_t addr) {
    asm volatile("ldmatrix.sync.aligned.m8n8.x4.trans.shared.b16 {%0,%1,%2,%3}, [%4];"
                 : "=r"(r[0]), "=r"(r[1]), "=r"(r[2]), "=r"(r[3]) : "r"(addr));
}

__device__ __forceinline__ void cp_async16(void* dst_smem, const void* src) {
    unsigned d = (unsigned)__cvta_generic_to_shared(dst_smem);
    asm volatile("cp.async.cg.shared.global [%0], [%1], 16;" :: "r"(d), "l"(src));
}
#define CP_COMMIT() asm volatile("cp.async.commit_group;")
#define CP_WAIT0()  asm volatile("cp.async.wait_group 0;")
#define CP_WAIT1()  asm volatile("cp.async.wait_group 1;")

__device__ __forceinline__ float ex2f(float x) {
    float r;
    asm("ex2.approx.f32 %0, %1;" : "=f"(r) : "f"(x));
    return r;
}
// pack (lo=x, hi=y) with saturate-to-max-finite (no inf on overflow)
__device__ __forceinline__ uint32_t h2u_sat(float x, float y) {
    uint32_t u;
    asm("cvt.rn.satfinite.f16x2.f32 %0, %1, %2;" : "=r"(u) : "f"(y), "f"(x));
    return u;
}

// ---------------------------------------------------------------------------
// Fused pre-pass: LayerNorm (x, ctx) + fp32->fp16 weight convert, one launch
// ---------------------------------------------------------------------------
__global__ __launch_bounds__(256) void prepass_k(
    const float* __restrict__ x,  const float* __restrict__ ctx,
    const float* __restrict__ nw, const float* __restrict__ nb,
    const float* __restrict__ cw, const float* __restrict__ cb,
    __half* __restrict__ xn, __half* __restrict__ cn,
    const float* __restrict__ wq, const float* __restrict__ wkv,
    const float* __restrict__ wo,
    __half* __restrict__ hq, __half* __restrict__ hkv, __half* __restrict__ ho)
{
    int blk = blockIdx.x;
    const int tid = threadIdx.x;

    if (blk >= 2 * RROWS) {
        const size_t i = ((size_t)(blk - 2 * RROWS) * 256 + tid) * 4;
        const float* src; __half* dst; size_t off;
        if (i < (size_t)1024 * 1024) { src = wq; dst = hq; off = i; }
        else if (i < (size_t)(1024 * 1024 + 1024 * 2048)) {
            src = wkv; dst = hkv; off = i - (size_t)1024 * 1024;
        } else { src = wo; dst = ho; off = i - (size_t)(1024 * 1024 + 1024 * 2048); }
        float4 v = *reinterpret_cast<const float4*>(src + off);
        __half2 h0 = __floats2half2_rn(v.x, v.y);
        __half2 h1 = __floats2half2_rn(v.z, v.w);
        uint2 u; memcpy(&u.x, &h0, 4); memcpy(&u.y, &h1, 4);
        *reinterpret_cast<uint2*>(dst + off) = u;
        return;
    }

    int row = blk;
    const float *xp, *w, *b; __half* y;
    if (row < RROWS) { xp = x; w = nw; b = nb; y = xn; }
    else { row -= RROWS; xp = ctx; w = cw; b = cb; y = cn; }

    const float* xr = xp + (size_t)row * DIMV;
    float4 v = reinterpret_cast<const float4*>(xr)[tid];
    float s  = v.x + v.y + v.z + v.w;
    float ss = v.x*v.x + v.y*v.y + v.z*v.z + v.w*v.w;
    #pragma unroll
    for (int o = 16; o > 0; o >>= 1) {
        s  += __shfl_xor_sync(0xffffffffu, s,  o);
        ss += __shfl_xor_sync(0xffffffffu, ss, o);
    }
    __shared__ float sm1[8], sm2[8];
    if ((tid & 31) == 0) { sm1[tid >> 5] = s; sm2[tid >> 5] = ss; }
    __syncthreads();
    float tot = 0.f, tot2 = 0.f;
    #pragma unroll
    for (int i = 0; i < 8; i++) { tot += sm1[i]; tot2 += sm2[i]; }
    const float mu  = tot * (1.0f / DIMV);
    const float var = tot2 * (1.0f / DIMV) - mu * mu;
    const float rs  = rsqrtf(var + LNEPS);
    float4 wv = reinterpret_cast<const float4*>(w)[tid];
    float4 bv = reinterpret_cast<const float4*>(b)[tid];
    __half2 h0 = __floats2half2_rn((v.x - mu) * rs * wv.x + bv.x,
                                   (v.y - mu) * rs * wv.y + bv.y);
    __half2 h1 = __floats2half2_rn((v.z - mu) * rs * wv.z + bv.z,
                                   (v.w - mu) * rs * wv.w + bv.w);
    uint2 u; memcpy(&u.x, &h0, 4); memcpy(&u.y, &h1, 4);
    *reinterpret_cast<uint2*>(y + (size_t)row * DIMV + tid * 4) = u;
}

// ---------------------------------------------------------------------------
// fp16 GEMM: C[128m x 128n tile] = alpha * A[128 x 1024] @ W[1024 x ndim]
// 128 threads, 4 warps (2x2), warp tile 64x64, BK=64 (half the barriers).
// 2-stage cp.async double buffer; compute per stage covers next-stage load.
// ---------------------------------------------------------------------------
#define GROWH 72                        // A smem row stride (halfs), 64 data
#define GTILEH (128 * GROWH)            // A stage: 9216 halfs
#define BROWH 136                       // B smem row stride (halfs), 128 data
#define BTILEH (64 * BROWH)             // B stage: 8704 halfs
#define GSTAGES 2
#define GT_SMEM_BYTES ((GSTAGES * GTILEH + GSTAGES * BTILEH) * 2)   // 71680 B

__device__ __forceinline__ void store2(__half* p, float x, float y) {
    *reinterpret_cast<__half2*>(p) = __floats2half2_rn(x, y);
}
__device__ __forceinline__ void store2(float* p, float x, float y) {
    *reinterpret_cast<float2*>(p) = make_float2(x, y);
}

template<typename OutT>
__device__ __forceinline__ void gemm_body(
    const __half* __restrict__ A, const __half* __restrict__ W,
    OutT* __restrict__ C, int ndim, int bm, int bn, float alpha)
{
    extern __shared__ __align__(16) __half smh[];
    __half* Asm = smh;
    __half* Bsm = smh + GSTAGES * GTILEH;
    const uint32_t sbA = (uint32_t)__cvta_generic_to_shared(Asm);
    const uint32_t sbB = (uint32_t)__cvta_generic_to_shared(Bsm);
    const int tid = threadIdx.x, warp = tid >> 5, lane = tid & 31;
    const int g = lane >> 2, t = lane & 3;
    const int m0 = (warp & 1) * 64, n0 = (warp >> 1) * 64;

    const __half* Ab = A + (size_t)(bm * 128) * 1024;
    const __half* Wb = W + bn * 128;

    float c[4][8][4];
    #pragma unroll
    for (int i = 0; i < 4; i++)
        #pragma unroll
        for (int j = 0; j < 8; j++)
            #pragma unroll
            for (int k = 0; k < 4; k++) c[i][j][k] = 0.f;

    auto prefetch = [&](int kt, int st) {
        __half* as = Asm + st * GTILEH;
        __half* bs = Bsm + st * BTILEH;
        // A: 128 rows x 64 halfs = 1024 x 16B chunks
        #pragma unroll
        for (int i = 0; i < 8; i++) {
            const int idx = tid + i * 128;
            const int row = idx >> 3, ch = idx & 7;
            cp_async16(as + row * GROWH + ch * 8, Ab + (size_t)row * 1024 + kt * 64 + ch * 8);
        }
        // B: 64 rows x 128 halfs = 1024 x 16B chunks
        #pragma unroll
        for (int i = 0; i < 8; i++) {
            const int idx = tid + i * 128;
            const int row = idx >> 4, ch = idx & 15;
            cp_async16(bs + row * BROWH + ch * 8, Wb + (size_t)(kt * 64 + row) * ndim + ch * 8);
        }
    };

    const int a_row = (lane & 7) + ((lane >> 3) & 1) * 8;
    const int a_col = (lane >> 4) * 8;
    const int b_row = (lane & 7) + ((lane >> 3) & 1) * 8;
    const int b_col = (lane >> 4) * 8;

    prefetch(0, 0); CP_COMMIT();

    for (int kt = 0; kt < 16; ++kt) {
        const int st = kt & 1;
        CP_WAIT0();
        __syncthreads();
        if (kt + 1 < 16) { prefetch(kt + 1, st ^ 1); CP_COMMIT(); }

        const uint32_t as = sbA + st * (GTILEH * 2);
        const uint32_t bs = sbB + st * (BTILEH * 2);
        #pragma unroll
        for (int kk = 0; kk < 4; kk++) {
            const int k0 = kk * 16;
            uint32_t a[4][4];
            #pragma unroll
            for (int mt = 0; mt < 4; mt++)
                ldsm_x4(a[mt], as + ((m0 + mt * 16 + a_row) * GROWH + k0 + a_col) * 2);
            uint32_t bfr[8][2];
            #pragma unroll
            for (int nb = 0; nb < 4; nb++) {
                uint32_t tmp[4];
                ldsm_x4_t(tmp, bs + ((k0 + b_row) * BROWH + n0 + nb * 16 + b_col) * 2);
                bfr[nb*2][0] = tmp[0]; bfr[nb*2][1] = tmp[1];
                bfr[nb*2+1][0] = tmp[2]; bfr[nb*2+1][1] = tmp[3];
            }
            #pragma unroll
            for (int mt = 0; mt < 4; mt++)
                #pragma unroll
                for (int nt = 0; nt < 8; nt++)
                    mma_f16(c[mt][nt], a[mt], bfr[nt]);
        }
    }

    #pragma unroll
    for (int mt = 0; mt < 4; mt++) {
        #pragma unroll
        for (int nt = 0; nt < 8; nt++) {
            const int row = bm * 128 + m0 + mt * 16 + g;
            const int col = bn * 128 + n0 + nt * 8 + 2 * t;
            store2(C + (size_t)row       * ndim + col, alpha * c[mt][nt][0], alpha * c[mt][nt][1]);
            store2(C + (size_t)(row + 8) * ndim + col, alpha * c[mt][nt][2], alpha * c[mt][nt][3]);
        }
    }
}

__global__ __launch_bounds__(128, 3) void gemm_qkv_k(
    const __half* __restrict__ xn, const __half* __restrict__ wq, __half* __restrict__ qo,
    const __half* __restrict__ cn, const __half* __restrict__ wkv, __half* __restrict__ kvo)
{
    int blk = blockIdx.x;
    if (blk < 256) {
        gemm_body<__half>(xn, wq, qo, 1024, blk >> 3, blk & 7, 0.125f * LOG2E);
    } else {
        blk -= 256;
        gemm_body<__half>(cn, wkv, kvo, 2048, blk >> 4, blk & 15, 1.0f);
    }
}

__global__ __launch_bounds__(128, 3) void gemm_o_k(
    const __half* __restrict__ A, const __half* __restrict__ wo, float* __restrict__ C)
{
    gemm_body<float>(A, wo, C, 1024, blockIdx.x >> 3, blockIdx.x & 7, 1.0f);
}

// ---------------------------------------------------------------------------
// Flash attention, zero-shift log2-domain softmax; 3-stage cp.async ring.
// 128 q-rows/block, 4 warps (32 q-rows each). No running max / rescale.
// ---------------------------------------------------------------------------
#define AROWH 72
#define ATILEH (64 * AROWH)
#define ASTAGES 3
#define AT_SMEM_BYTES (2 * ASTAGES * ATILEH * 2 + ASTAGES * 64 * 4)

__global__ __launch_bounds__(128) void attn_k(
    const __half* __restrict__ q, const __half* __restrict__ kv,
    const int* __restrict__ mask, __half* __restrict__ out)
{
    extern __shared__ __align__(16) __half sha[];
    __half* Ks = sha;                            // [3][64][AROWH]
    __half* Vs = sha + ASTAGES * ATILEH;         // [3][64][AROWH]
    float*  mb = reinterpret_cast<float*>(sha + 2 * ASTAGES * ATILEH);  // [3][64]
    const uint32_t sb = (uint32_t)__cvta_generic_to_shared(sha);

    const int tid = threadIdx.x, warp = tid >> 5, lane = tid & 31;
    const int g = lane >> 2, t = lane & 3;
    const int qt = blockIdx.x, bh = blockIdx.y;
    const int b = bh >> 4, h = bh & 15;

    const __half* kvbase = kv + ((size_t)b * MSEQ) * (2 * INNERV) + h * DH;

    auto prefetch = [&](int kt, int buf) {
        const __half* kb = kvbase + (size_t)(kt * 64) * (2 * INNERV);
        __half* kd = Ks + buf * ATILEH;
        __half* vd = Vs + buf * ATILEH;
        #pragma unroll
        for (int i = 0; i < 4; i++) {
            const int idx = tid + i * 128;
            const int r = idx >> 3, ch = (idx & 7) * 8;
            const __half* src = kb + (size_t)r * (2 * INNERV) + ch;
            cp_async16(kd + r * AROWH + ch, src);
            cp_async16(vd + r * AROWH + ch, src + INNERV);
        }
    };

    prefetch(0, 0); CP_COMMIT();
    prefetch(1, 1); CP_COMMIT();

    // mask scan: is this batch's mask fully true?
    bool lok = true;
    #pragma unroll
    for (int i = 0; i < 4; i++) {
        int4 mv = reinterpret_cast<const int4*>(mask + (size_t)b * MSEQ)[tid + i * 128];
        lok &= (mv.x != 0) & (mv.y != 0) & (mv.z != 0) & (mv.w != 0);
    }
    const int all_true = __syncthreads_and(lok);
    if (all_true) {
        if (tid < 64) { mb[tid] = 0.f; mb[64 + tid] = 0.f; mb[128 + tid] = 0.f; }
    } else if (tid < 64) {
        mb[tid]      = mask[(size_t)b * MSEQ + tid]      ? 0.f : -1e30f;
        mb[64 + tid] = mask[(size_t)b * MSEQ + 64 + tid] ? 0.f : -1e30f;
    }

    // Q fragments for 2 m-tiles (scale*log2e folded at q GEMM)
    uint32_t qf[2][4][4];
    {
        const __half* qb = q + (size_t)(b * NSEQ + qt * 128 + warp * 32) * INNERV + h * DH;
        #pragma unroll
        for (int mt = 0; mt < 2; mt++) {
            const __half* qm = qb + (size_t)(mt * 16) * INNERV;
            #pragma unroll
            for (int kk = 0; kk < 4; kk++) {
                qf[mt][kk][0] = *reinterpret_cast<const uint32_t*>(qm + (size_t)g       * INNERV + kk * 16 + 2 * t);
                qf[mt][kk][1] = *reinterpret_cast<const uint32_t*>(qm + (size_t)(g + 8) * INNERV + kk * 16 + 2 * t);
                qf[mt][kk][2] = *reinterpret_cast<const uint32_t*>(qm + (size_t)g       * INNERV + kk * 16 + 2 * t + 8);
                qf[mt][kk][3] = *reinterpret_cast<const uint32_t*>(qm + (size_t)(g + 8) * INNERV + kk * 16 + 2 * t + 8);
            }
        }
    }

    const int kb_row = (lane & 7) + (lane >> 4) * 8;
    const int kb_col = ((lane >> 3) & 1) * 8;
    const int vb_row = (lane & 7) + ((lane >> 3) & 1) * 8;
    const int vb_col = (lane >> 4) * 8;

    float lst[2][2] = {{0.f, 0.f}, {0.f, 0.f}};
    float o[2][8][4];
    #pragma unroll
    for (int mt = 0; mt < 2; mt++)
        #pragma unroll
        for (int i = 0; i < 8; i++)
            #pragma unroll
            for (int j = 0; j < 4; j++) o[mt][i][j] = 0.f;

    const int NKT = MSEQ / 64;
    for (int kt = 0; kt < NKT; ++kt) {
        const int cur = kt % ASTAGES;
        CP_WAIT1();
        __syncthreads();
        if (kt + 2 < NKT) {
            prefetch(kt + 2, (kt + 2) % ASTAGES);
            if (!all_true && tid < 64)
                mb[((kt + 2) % ASTAGES) * 64 + tid] =
                    mask[(size_t)b * MSEQ + (kt + 2) * 64 + tid] ? 0.f : -1e30f;
        }
        CP_COMMIT();

        const uint32_t Kc = sb + cur * (ATILEH * 2);
        const uint32_t Vc = sb + (ASTAGES + cur) * (ATILEH * 2);
        const float* mbc = mb + cur * 64;

        // S = Q (32x64) @ K^T
        float s[2][8][4];
        #pragma unroll
        for (int mt = 0; mt < 2; mt++)
            #pragma unroll
            for (int i = 0; i < 8; i++)
                #pragma unroll
                for (int j = 0; j < 4; j++) s[mt][i][j] = 0.f;

        #pragma unroll
        for (int kk = 0; kk < 4; kk++) {
            uint32_t kf[8][2];
            #pragma unroll
            for (int nb = 0; nb < 4; nb++) {
                uint32_t tmp[4];
                ldsm_x4(tmp, Kc + ((nb * 16 + kb_row) * AROWH + kk * 16 + kb_col) * 2);
                kf[nb*2][0] = tmp[0]; kf[nb*2][1] = tmp[1];
                kf[nb*2+1][0] = tmp[2]; kf[nb*2+1][1] = tmp[3];
            }
            #pragma unroll
            for (int nt = 0; nt < 8; nt++) {
                mma_f16(s[0][nt], qf[0][kk], kf[nt]);
                mma_f16(s[1][nt], qf[1][kk], kf[nt]);
            }
        }

        // p = exp2(s + bias); accumulate l
        #pragma unroll
        for (int mt = 0; mt < 2; mt++) {
            #pragma unroll
            for (int nt = 0; nt < 8; nt++) {
                const float b0v = mbc[nt * 8 + 2 * t], b1v = mbc[nt * 8 + 2 * t + 1];
                s[mt][nt][0] = ex2f(s[mt][nt][0] + b0v);
                s[mt][nt][1] = ex2f(s[mt][nt][1] + b1v);
                s[mt][nt][2] = ex2f(s[mt][nt][2] + b0v);
                s[mt][nt][3] = ex2f(s[mt][nt][3] + b1v);
                lst[mt][0] += s[mt][nt][0] + s[mt][nt][1];
                lst[mt][1] += s[mt][nt][2] + s[mt][nt][3];
            }
        }

        // O += P @ V
        #pragma unroll
        for (int kk = 0; kk < 4; kk++) {
            uint32_t pa[2][4];
            #pragma unroll
            for (int mt = 0; mt < 2; mt++) {
                pa[mt][0] = h2u_sat(s[mt][2*kk][0],   s[mt][2*kk][1]);
                pa[mt][1] = h2u_sat(s[mt][2*kk][2],   s[mt][2*kk][3]);
                pa[mt][2] = h2u_sat(s[mt][2*kk+1][0], s[mt][2*kk+1][1]);
                pa[mt][3] = h2u_sat(s[mt][2*kk+1][2], s[mt][2*kk+1][3]);
            }
            uint32_t vf[8][2];
            #pragma unroll
            for (int nb = 0; nb < 4; nb++) {
                uint32_t tmp[4];
                ldsm_x4_t(tmp, Vc + ((kk * 16 + vb_row) * AROWH + nb * 16 + vb_col) * 2);
                vf[nb*2][0] = tmp[0]; vf[nb*2][1] = tmp[1];
                vf[nb*2+1][0] = tmp[2]; vf[nb*2+1][1] = tmp[3];
            }
            #pragma unroll
            for (int nt = 0; nt < 8; nt++) {
                mma_f16(o[0][nt], pa[0], vf[nt]);
                mma_f16(o[1][nt], pa[1], vf[nt]);
            }
        }
    }

    // final lane reduction of row sums
    #pragma unroll
    for (int mt = 0; mt < 2; mt++) {
        #pragma unroll
        for (int j = 0; j < 2; j++) {
            lst[mt][j] += __shfl_xor_sync(0xffffffffu, lst[mt][j], 1);
            lst[mt][j] += __shfl_xor_sync(0xffffffffu, lst[mt][j], 2);
        }
    }

    #pragma unroll
    for (int mt = 0; mt < 2; mt++) {
        const float inv0 = 1.f / lst[mt][0], inv1 = 1.f / lst[mt][1];
        const int row0 = b * NSEQ + qt * 128 + warp * 32 + mt * 16 + g;
        #pragma unroll
        for (int nt = 0; nt < 8; nt++) {
            const int col = h * DH + nt * 8 + 2 * t;
            *reinterpret_cast<__half2*>(&out[(size_t)row0 * INNERV + col]) =
                __floats2half2_rn(o[mt][nt][0] * inv0, o[mt][nt][1] * inv0);
            *reinterpret_cast<__half2*>(&out[(size_t)(row0 + 8) * INNERV + col]) =
                __floats2half2_rn(o[mt][nt][2] * inv1, o[mt][nt][3] * inv1);
        }
    }
}

// ---------------------------------------------------------------------------
// Launch
// ---------------------------------------------------------------------------
extern "C" void kernel_launch(void* const* d_in, const int* in_sizes, int n_in,
                              void* d_out, int out_size)
{
    (void)in_sizes; (void)n_in; (void)out_size;
    const float* x    = (const float*)d_in[0];
    const float* ctx  = (const float*)d_in[1];
    const float* nw   = (const float*)d_in[2];
    const float* nb   = (const float*)d_in[3];
    const float* cw   = (const float*)d_in[4];
    const float* cb   = (const float*)d_in[5];
    const float* Wq   = (const float*)d_in[6];
    const float* Wkv  = (const float*)d_in[7];
    const float* Wo   = (const float*)d_in[8];
    const int*   mask = (const int*)d_in[9];
    float* out = (float*)d_out;

    __half *xn, *cn, *qb, *kvb, *ao, *hwq, *hwkv, *hwo;
    cudaGetSymbolAddress((void**)&xn,   g_xn);
    cudaGetSymbolAddress((void**)&cn,   g_cn);
    cudaGetSymbolAddress((void**)&qb,   g_q);
    cudaGetSymbolAddress((void**)&kvb,  g_kv);
    cudaGetSymbolAddress((void**)&ao,   g_ao);
    cudaGetSymbolAddress((void**)&hwq,  g_wq);
    cudaGetSymbolAddress((void**)&hwkv, g_wkv);
    cudaGetSymbolAddress((void**)&hwo,  g_wo);

    // fused LN + weight convert
    prepass_k<<<2 * RROWS + 4096, 256>>>(x, ctx, nw, nb, cw, cb, xn, cn,
                                         Wq, Wkv, Wo, hwq, hwkv, hwo);

    cudaFuncSetAttribute(gemm_qkv_k, cudaFuncAttributeMaxDynamicSharedMemorySize, GT_SMEM_BYTES);
    cudaFuncSetAttribute(gemm_o_k,   cudaFuncAttributeMaxDynamicSharedMemorySize, GT_SMEM_BYTES);

    gemm_qkv_k<<<768, 128, GT_SMEM_BYTES>>>(xn, hwq, qb, cn, hwkv, kvb);

    cudaFuncSetAttribute(attn_k, cudaFuncAttributeMaxDynamicSharedMemorySize, AT_SMEM_BYTES);
    attn_k<<<dim3(NSEQ / 128, BATCH * HEADS), 128, AT_SMEM_BYTES>>>(qb, kvb, mask, ao);

    gemm_o_k<<<256, 128, GT_SMEM_BYTES>>>(ao, hwo, out);
}

// round 17
// speedup vs baseline: 1.0813x; 1.0181x over previous
#include <cuda_runtime.h>
#include <cuda_fp16.h>
#include <cstdint>
#include <cstddef>
#include <cstring>

// Problem constants
#define DIMV   1024
#define HEADS  16
#define DH     64
#define INNERV 1024
#define BATCH  2
#define NSEQ   2048
#define MSEQ   2048
#define RROWS  4096   // BATCH * NSEQ
#define LNEPS  1e-5f
#define LOG2E  1.44269504088896f

// Scratch (device globals: allocation-free per harness rules)
__device__ __half g_xn[RROWS * DIMV];
__device__ __half g_cn[RROWS * DIMV];
__device__ __half g_q [RROWS * INNERV];
__device__ __half g_kv[RROWS * 2 * INNERV];
__device__ __half g_ao[RROWS * INNERV];
__device__ __half g_wq [1024 * 1024];
__device__ __half g_wkv[1024 * 2048];
__device__ __half g_wo [1024 * 1024];

// ---------------------------------------------------------------------------
// Primitives
// ---------------------------------------------------------------------------
__device__ __forceinline__ void mma_f16(float c[4], const uint32_t a[4], const uint32_t b[2]) {
    asm volatile(
        "mma.sync.aligned.m16n8k16.row.col.f32.f16.f16.f32 "
        "{%0,%1,%2,%3}, {%4,%5,%6,%7}, {%8,%9}, {%0,%1,%2,%3};\n"
        : "+f"(c[0]), "+f"(c[1]), "+f"(c[2]), "+f"(c[3])
        : "r"(a[0]), "r"(a[1]), "r"(a[2]), "r"(a[3]), "r"(b[0]), "r"(b[1]));
}

__device__ __forceinline__ void ldsm_x4(uint32_t r[4], uint32_t addr) {
    asm volatile("ldmatrix.sync.aligned.m8n8.x4.shared.b16 {%0,%1,%2,%3}, [%4];"
                 : "=r"(r[0]), "=r"(r[1]), "=r"(r[2]), "=r"(r[3]) : "r"(addr));
}
__device__ __forceinline__ void ldsm_x4_t(uint32_t r[4], uint32_t addr) {
    asm volatile("ldmatrix.sync.aligned.m8n8.x4.trans.shared.b16 {%0,%1,%2,%3}, [%4];"
                 : "=r"(r[0]), "=r"(r[1]), "=r"(r[2]), "=r"(r[3]) : "r"(addr));
}

__device__ __forceinline__ void cp_async16(void* dst_smem, const void* src) {
    unsigned d = (unsigned)__cvta_generic_to_shared(dst_smem);
    asm volatile("cp.async.cg.shared.global [%0], [%1], 16;" :: "r"(d), "l"(src));
}
#define CP_COMMIT() asm volatile("cp.async.commit_group;")
#define CP_WAIT0()  asm volatile("cp.async.wait_group 0;")
#define CP_WAIT1()  asm volatile("cp.async.wait_group 1;")

__device__ __forceinline__ float ex2f(float x) {
    float r;
    asm("ex2.approx.f32 %0, %1;" : "=f"(r) : "f"(x));
    return r;
}
// pack (lo=x, hi=y) with saturate-to-max-finite (no inf on overflow)
__device__ __forceinline__ uint32_t h2u_sat(float x, float y) {
    uint32_t u;
    asm("cvt.rn.satfinite.f16x2.f32 %0, %1, %2;" : "=r"(u) : "f"(y), "f"(x));
    return u;
}

// ---------------------------------------------------------------------------
// Fused pre-pass: LayerNorm (x, ctx) + fp32->fp16 weight convert, one launch
// ---------------------------------------------------------------------------
__global__ __launch_bounds__(256) void prepass_k(
    const float* __restrict__ x,  const float* __restrict__ ctx,
    const float* __restrict__ nw, const float* __restrict__ nb,
    const float* __restrict__ cw, const float* __restrict__ cb,
    __half* __restrict__ xn, __half* __restrict__ cn,
    const float* __restrict__ wq, const float* __restrict__ wkv,
    const float* __restrict__ wo,
    __half* __restrict__ hq, __half* __restrict__ hkv, __half* __restrict__ ho)
{
    int blk = blockIdx.x;
    const int tid = threadIdx.x;

    if (blk >= 2 * RROWS) {
        const size_t i = ((size_t)(blk - 2 * RROWS) * 256 + tid) * 4;
        const float* src; __half* dst; size_t off;
        if (i < (size_t)1024 * 1024) { src = wq; dst = hq; off = i; }
        else if (i < (size_t)(1024 * 1024 + 1024 * 2048)) {
            src = wkv; dst = hkv; off = i - (size_t)1024 * 1024;
        } else { src = wo; dst = ho; off = i - (size_t)(1024 * 1024 + 1024 * 2048); }
        float4 v = *reinterpret_cast<const float4*>(src + off);
        __half2 h0 = __floats2half2_rn(v.x, v.y);
        __half2 h1 = __floats2half2_rn(v.z, v.w);
        uint2 u; memcpy(&u.x, &h0, 4); memcpy(&u.y, &h1, 4);
        *reinterpret_cast<uint2*>(dst + off) = u;
        return;
    }

    int row = blk;
    const float *xp, *w, *b; __half* y;
    if (row < RROWS) { xp = x; w = nw; b = nb; y = xn; }
    else { row -= RROWS; xp = ctx; w = cw; b = cb; y = cn; }

    const float* xr = xp + (size_t)row * DIMV;
    float4 v = reinterpret_cast<const float4*>(xr)[tid];
    float s  = v.x + v.y + v.z + v.w;
    float ss = v.x*v.x + v.y*v.y + v.z*v.z + v.w*v.w;
    #pragma unroll
    for (int o = 16; o > 0; o >>= 1) {
        s  += __shfl_xor_sync(0xffffffffu, s,  o);
        ss += __shfl_xor_sync(0xffffffffu, ss, o);
    }
    __shared__ float sm1[8], sm2[8];
    if ((tid & 31) == 0) { sm1[tid >> 5] = s; sm2[tid >> 5] = ss; }
    __syncthreads();
    float tot = 0.f, tot2 = 0.f;
    #pragma unroll
    for (int i = 0; i < 8; i++) { tot += sm1[i]; tot2 += sm2[i]; }
    const float mu  = tot * (1.0f / DIMV);
    const float var = tot2 * (1.0f / DIMV) - mu * mu;
    const float rs  = rsqrtf(var + LNEPS);
    float4 wv = reinterpret_cast<const float4*>(w)[tid];
    float4 bv = reinterpret_cast<const float4*>(b)[tid];
    __half2 h0 = __floats2half2_rn((v.x - mu) * rs * wv.x + bv.x,
                                   (v.y - mu) * rs * wv.y + bv.y);
    __half2 h1 = __floats2half2_rn((v.z - mu) * rs * wv.z + bv.z,
                                   (v.w - mu) * rs * wv.w + bv.w);
    uint2 u; memcpy(&u.x, &h0, 4); memcpy(&u.y, &h1, 4);
    *reinterpret_cast<uint2*>(y + (size_t)row * DIMV + tid * 4) = u;
}

// ---------------------------------------------------------------------------
// fp16 GEMM: C[128m x 64n tile] = alpha * A[128 x 1024] @ W[1024 x ndim]
// 128 threads, 4 warps (2x2), warp tile 64x32, BK=64, 2-stage cp.async.
// Small smem footprint (55.3 KB) -> 4 CTAs/SM = 16 warps for latency hiding.
// ---------------------------------------------------------------------------
#define GROWH 72                        // A smem row stride (halfs), 64 data
#define GTILEH (128 * GROWH)            // A stage: 9216 halfs
#define BROWH 72                        // B smem row stride (halfs), 64 data
#define BTILEH (64 * BROWH)             // B stage: 4608 halfs
#define GSTAGES 2
#define GT_SMEM_BYTES ((GSTAGES * GTILEH + GSTAGES * BTILEH) * 2)   // 55296 B

__device__ __forceinline__ void store2(__half* p, float x, float y) {
    *reinterpret_cast<__half2*>(p) = __floats2half2_rn(x, y);
}
__device__ __forceinline__ void store2(float* p, float x, float y) {
    *reinterpret_cast<float2*>(p) = make_float2(x, y);
}

template<typename OutT>
__device__ __forceinline__ void gemm_body(
    const __half* __restrict__ A, const __half* __restrict__ W,
    OutT* __restrict__ C, int ndim, int bm, int bn, float alpha)
{
    extern __shared__ __align__(16) __half smh[];
    __half* Asm = smh;
    __half* Bsm = smh + GSTAGES * GTILEH;
    const uint32_t sbA = (uint32_t)__cvta_generic_to_shared(Asm);
    const uint32_t sbB = (uint32_t)__cvta_generic_to_shared(Bsm);
    const int tid = threadIdx.x, warp = tid >> 5, lane = tid & 31;
    const int g = lane >> 2, t = lane & 3;
    const int m0 = (warp & 1) * 64, n0 = (warp >> 1) * 32;

    const __half* Ab = A + (size_t)(bm * 128) * 1024;
    const __half* Wb = W + bn * 64;

    float c[4][4][4];
    #pragma unroll
    for (int i = 0; i < 4; i++)
        #pragma unroll
        for (int j = 0; j < 4; j++)
            #pragma unroll
            for (int k = 0; k < 4; k++) c[i][j][k] = 0.f;

    auto prefetch = [&](int kt, int st) {
        __half* as = Asm + st * GTILEH;
        __half* bs = Bsm + st * BTILEH;
        // A: 128 rows x 64 halfs = 1024 x 8h chunks
        #pragma unroll
        for (int i = 0; i < 8; i++) {
            const int idx = tid + i * 128;
            const int row = idx >> 3, ch = idx & 7;
            cp_async16(as + row * GROWH + ch * 8, Ab + (size_t)row * 1024 + kt * 64 + ch * 8);
        }
        // B: 64 rows x 64 halfs = 512 x 8h chunks
        #pragma unroll
        for (int i = 0; i < 4; i++) {
            const int idx = tid + i * 128;
            const int row = idx >> 3, ch = idx & 7;
            cp_async16(bs + row * BROWH + ch * 8, Wb + (size_t)(kt * 64 + row) * ndim + ch * 8);
        }
    };

    const int a_row = (lane & 7) + ((lane >> 3) & 1) * 8;
    const int a_col = (lane >> 4) * 8;
    const int b_row = (lane & 7) + ((lane >> 3) & 1) * 8;
    const int b_col = (lane >> 4) * 8;

    prefetch(0, 0); CP_COMMIT();

    for (int kt = 0; kt < 16; ++kt) {
        const int st = kt & 1;
        CP_WAIT0();
        __syncthreads();
        if (kt + 1 < 16) { prefetch(kt + 1, st ^ 1); CP_COMMIT(); }

        const uint32_t as = sbA + st * (GTILEH * 2);
        const uint32_t bs = sbB + st * (BTILEH * 2);
        #pragma unroll
        for (int kk = 0; kk < 4; kk++) {
            const int k0 = kk * 16;
            uint32_t a[4][4];
            #pragma unroll
            for (int mt = 0; mt < 4; mt++)
                ldsm_x4(a[mt], as + ((m0 + mt * 16 + a_row) * GROWH + k0 + a_col) * 2);
            uint32_t bfr[4][2];
            #pragma unroll
            for (int nb = 0; nb < 2; nb++) {
                uint32_t tmp[4];
                ldsm_x4_t(tmp, bs + ((k0 + b_row) * BROWH + n0 + nb * 16 + b_col) * 2);
                bfr[nb*2][0] = tmp[0]; bfr[nb*2][1] = tmp[1];
                bfr[nb*2+1][0] = tmp[2]; bfr[nb*2+1][1] = tmp[3];
            }
            #pragma unroll
            for (int mt = 0; mt < 4; mt++)
                #pragma unroll
                for (int nt = 0; nt < 4; nt++)
                    mma_f16(c[mt][nt], a[mt], bfr[nt]);
        }
    }

    #pragma unroll
    for (int mt = 0; mt < 4; mt++) {
        #pragma unroll
        for (int nt = 0; nt < 4; nt++) {
            const int row = bm * 128 + m0 + mt * 16 + g;
            const int col = bn * 64 + n0 + nt * 8 + 2 * t;
            store2(C + (size_t)row       * ndim + col, alpha * c[mt][nt][0], alpha * c[mt][nt][1]);
            store2(C + (size_t)(row + 8) * ndim + col, alpha * c[mt][nt][2], alpha * c[mt][nt][3]);
        }
    }
}

// Fused q + kv GEMM: blocks [0,512) -> q (N=1024, 16 n-tiles),
// [512, 1536) -> kv (N=2048, 32 n-tiles)
__global__ __launch_bounds__(128, 4) void gemm_qkv_k(
    const __half* __restrict__ xn, const __half* __restrict__ wq, __half* __restrict__ qo,
    const __half* __restrict__ cn, const __half* __restrict__ wkv, __half* __restrict__ kvo)
{
    int blk = blockIdx.x;
    if (blk < 512) {
        gemm_body<__half>(xn, wq, qo, 1024, blk >> 4, blk & 15, 0.125f * LOG2E);
    } else {
        blk -= 512;
        gemm_body<__half>(cn, wkv, kvo, 2048, blk >> 5, blk & 31, 1.0f);
    }
}

__global__ __launch_bounds__(128, 4) void gemm_o_k(
    const __half* __restrict__ A, const __half* __restrict__ wo, float* __restrict__ C)
{
    gemm_body<float>(A, wo, C, 1024, blockIdx.x >> 4, blockIdx.x & 15, 1.0f);
}

// ---------------------------------------------------------------------------
// Flash attention, zero-shift log2-domain softmax; 3-stage cp.async ring.
// 128 q-rows/block, 4 warps (32 q-rows each). No running max / rescale.
// ---------------------------------------------------------------------------
#define AROWH 72
#define ATILEH (64 * AROWH)
#define ASTAGES 3
#define AT_SMEM_BYTES (2 * ASTAGES * ATILEH * 2 + ASTAGES * 64 * 4)

__global__ __launch_bounds__(128) void attn_k(
    const __half* __restrict__ q, const __half* __restrict__ kv,
    const int* __restrict__ mask, __half* __restrict__ out)
{
    extern __shared__ __align__(16) __half sha[];
    __half* Ks = sha;                            // [3][64][AROWH]
    __half* Vs = sha + ASTAGES * ATILEH;         // [3][64][AROWH]
    float*  mb = reinterpret_cast<float*>(sha + 2 * ASTAGES * ATILEH);  // [3][64]
    const uint32_t sb = (uint32_t)__cvta_generic_to_shared(sha);

    const int tid = threadIdx.x, warp = tid >> 5, lane = tid & 31;
    const int g = lane >> 2, t = lane & 3;
    const int qt = blockIdx.x, bh = blockIdx.y;
    const int b = bh >> 4, h = bh & 15;

    const __half* kvbase = kv + ((size_t)b * MSEQ) * (2 * INNERV) + h * DH;

    auto prefetch = [&](int kt, int buf) {
        const __half* kb = kvbase + (size_t)(kt * 64) * (2 * INNERV);
        __half* kd = Ks + buf * ATILEH;
        __half* vd = Vs + buf * ATILEH;
        #pragma unroll
        for (int i = 0; i < 4; i++) {
            const int idx = tid + i * 128;
            const int r = idx >> 3, ch = (idx & 7) * 8;
            const __half* src = kb + (size_t)r * (2 * INNERV) + ch;
            cp_async16(kd + r * AROWH + ch, src);
            cp_async16(vd + r * AROWH + ch, src + INNERV);
        }
    };

    prefetch(0, 0); CP_COMMIT();
    prefetch(1, 1); CP_COMMIT();

    // mask scan: is this batch's mask fully true?
    bool lok = true;
    #pragma unroll
    for (int i = 0; i < 4; i++) {
        int4 mv = reinterpret_cast<const int4*>(mask + (size_t)b * MSEQ)[tid + i * 128];
        lok &= (mv.x != 0) & (mv.y != 0) & (mv.z != 0) & (mv.w != 0);
    }
    const int all_true = __syncthreads_and(lok);
    if (all_true) {
        if (tid < 64) { mb[tid] = 0.f; mb[64 + tid] = 0.f; mb[128 + tid] = 0.f; }
    } else if (tid < 64) {
        mb[tid]      = mask[(size_t)b * MSEQ + tid]      ? 0.f : -1e30f;
        mb[64 + tid] = mask[(size_t)b * MSEQ + 64 + tid] ? 0.f : -1e30f;
    }

    // Q fragments for 2 m-tiles (scale*log2e folded at q GEMM)
    uint32_t qf[2][4][4];
    {
        const __half* qb = q + (size_t)(b * NSEQ + qt * 128 + warp * 32) * INNERV + h * DH;
        #pragma unroll
        for (int mt = 0; mt < 2; mt++) {
            const __half* qm = qb + (size_t)(mt * 16) * INNERV;
            #pragma unroll
            for (int kk = 0; kk < 4; kk++) {
                qf[mt][kk][0] = *reinterpret_cast<const uint32_t*>(qm + (size_t)g       * INNERV + kk * 16 + 2 * t);
                qf[mt][kk][1] = *reinterpret_cast<const uint32_t*>(qm + (size_t)(g + 8) * INNERV + kk * 16 + 2 * t);
                qf[mt][kk][2] = *reinterpret_cast<const uint32_t*>(qm + (size_t)g       * INNERV + kk * 16 + 2 * t + 8);
                qf[mt][kk][3] = *reinterpret_cast<const uint32_t*>(qm + (size_t)(g + 8) * INNERV + kk * 16 + 2 * t + 8);
            }
        }
    }

    const int kb_row = (lane & 7) + (lane >> 4) * 8;
    const int kb_col = ((lane >> 3) & 1) * 8;
    const int vb_row = (lane & 7) + ((lane >> 3) & 1) * 8;
    const int vb_col = (lane >> 4) * 8;

    float lst[2][2] = {{0.f, 0.f}, {0.f, 0.f}};
    float o[2][8][4];
    #pragma unroll
    for (int mt = 0; mt < 2; mt++)
        #pragma unroll
        for (int i = 0; i < 8; i++)
            #pragma unroll
            for (int j = 0; j < 4; j++) o[mt][i][j] = 0.f;

    const int NKT = MSEQ / 64;
    for (int kt = 0; kt < NKT; ++kt) {
        const int cur = kt % ASTAGES;
        CP_WAIT1();
        __syncthreads();
        if (kt + 2 < NKT) {
            prefetch(kt + 2, (kt + 2) % ASTAGES);
            if (!all_true && tid < 64)
                mb[((kt + 2) % ASTAGES) * 64 + tid] =
                    mask[(size_t)b * MSEQ + (kt + 2) * 64 + tid] ? 0.f : -1e30f;
        }
        CP_COMMIT();

        const uint32_t Kc = sb + cur * (ATILEH * 2);
        const uint32_t Vc = sb + (ASTAGES + cur) * (ATILEH * 2);
        const float* mbc = mb + cur * 64;

        // S = Q (32x64) @ K^T
        float s[2][8][4];
        #pragma unroll
        for (int mt = 0; mt < 2; mt++)
            #pragma unroll
            for (int i = 0; i < 8; i++)
                #pragma unroll
                for (int j = 0; j < 4; j++) s[mt][i][j] = 0.f;

        #pragma unroll
        for (int kk = 0; kk < 4; kk++) {
            uint32_t kf[8][2];
            #pragma unroll
            for (int nb = 0; nb < 4; nb++) {
                uint32_t tmp[4];
                ldsm_x4(tmp, Kc + ((nb * 16 + kb_row) * AROWH + kk * 16 + kb_col) * 2);
                kf[nb*2][0] = tmp[0]; kf[nb*2][1] = tmp[1];
                kf[nb*2+1][0] = tmp[2]; kf[nb*2+1][1] = tmp[3];
            }
            #pragma unroll
            for (int nt = 0; nt < 8; nt++) {
                mma_f16(s[0][nt], qf[0][kk], kf[nt]);
                mma_f16(s[1][nt], qf[1][kk], kf[nt]);
            }
        }

        // p = exp2(s + bias); accumulate l
        #pragma unroll
        for (int mt = 0; mt < 2; mt++) {
            #pragma unroll
            for (int nt = 0; nt < 8; nt++) {
                const float b0v = mbc[nt * 8 + 2 * t], b1v = mbc[nt * 8 + 2 * t + 1];
                s[mt][nt][0] = ex2f(s[mt][nt][0] + b0v);
                s[mt][nt][1] = ex2f(s[mt][nt][1] + b1v);
                s[mt][nt][2] = ex2f(s[mt][nt][2] + b0v);
                s[mt][nt][3] = ex2f(s[mt][nt][3] + b1v);
                lst[mt][0] += s[mt][nt][0] + s[mt][nt][1];
                lst[mt][1] += s[mt][nt][2] + s[mt][nt][3];
            }
        }

        // O += P @ V
        #pragma unroll
        for (int kk = 0; kk < 4; kk++) {
            uint32_t pa[2][4];
            #pragma unroll
            for (int mt = 0; mt < 2; mt++) {
                pa[mt][0] = h2u_sat(s[mt][2*kk][0],   s[mt][2*kk][1]);
                pa[mt][1] = h2u_sat(s[mt][2*kk][2],   s[mt][2*kk][3]);
                pa[mt][2] = h2u_sat(s[mt][2*kk+1][0], s[mt][2*kk+1][1]);
                pa[mt][3] = h2u_sat(s[mt][2*kk+1][2], s[mt][2*kk+1][3]);
            }
            uint32_t vf[8][2];
            #pragma unroll
            for (int nb = 0; nb < 4; nb++) {
                uint32_t tmp[4];
                ldsm_x4_t(tmp, Vc + ((kk * 16 + vb_row) * AROWH + nb * 16 + vb_col) * 2);
                vf[nb*2][0] = tmp[0]; vf[nb*2][1] = tmp[1];
                vf[nb*2+1][0] = tmp[2]; vf[nb*2+1][1] = tmp[3];
            }
            #pragma unroll
            for (int nt = 0; nt < 8; nt++) {
                mma_f16(o[0][nt], pa[0], vf[nt]);
                mma_f16(o[1][nt], pa[1], vf[nt]);
            }
        }
    }

    // final lane reduction of row sums
    #pragma unroll
    for (int mt = 0; mt < 2; mt++) {
        #pragma unroll
        for (int j = 0; j < 2; j++) {
            lst[mt][j] += __shfl_xor_sync(0xffffffffu, lst[mt][j], 1);
            lst[mt][j] += __shfl_xor_sync(0xffffffffu, lst[mt][j], 2);
        }
    }

    #pragma unroll
    for (int mt = 0; mt < 2; mt++) {
        const float inv0 = 1.f / lst[mt][0], inv1 = 1.f / lst[mt][1];
        const int row0 = b * NSEQ + qt * 128 + warp * 32 + mt * 16 + g;
        #pragma unroll
        for (int nt = 0; nt < 8; nt++) {
            const int col = h * DH + nt * 8 + 2 * t;
            *reinterpret_cast<__half2*>(&out[(size_t)row0 * INNERV + col]) =
                __floats2half2_rn(o[mt][nt][0] * inv0, o[mt][nt][1] * inv0);
            *reinterpret_cast<__half2*>(&out[(size_t)(row0 + 8) * INNERV + col]) =
                __floats2half2_rn(o[mt][nt][2] * inv1, o[mt][nt][3] * inv1);
        }
    }
}

// ---------------------------------------------------------------------------
// Launch
// ---------------------------------------------------------------------------
extern "C" void kernel_launch(void* const* d_in, const int* in_sizes, int n_in,
                              void* d_out, int out_size)
{
    (void)in_sizes; (void)n_in; (void)out_size;
    const float* x    = (const float*)d_in[0];
    const float* ctx  = (const float*)d_in[1];
    const float* nw   = (const float*)d_in[2];
    const float* nb   = (const float*)d_in[3];
    const float* cw   = (const float*)d_in[4];
    const float* cb   = (const float*)d_in[5];
    const float* Wq   = (const float*)d_in[6];
    const float* Wkv  = (const float*)d_in[7];
    const float* Wo   = (const float*)d_in[8];
    const int*   mask = (const int*)d_in[9];
    float* out = (float*)d_out;

    __half *xn, *cn, *qb, *kvb, *ao, *hwq, *hwkv, *hwo;
    cudaGetSymbolAddress((void**)&xn,   g_xn);
    cudaGetSymbolAddress((void**)&cn,   g_cn);
    cudaGetSymbolAddress((void**)&qb,   g_q);
    cudaGetSymbolAddress((void**)&kvb,  g_kv);
    cudaGetSymbolAddress((void**)&ao,   g_ao);
    cudaGetSymbolAddress((void**)&hwq,  g_wq);
    cudaGetSymbolAddress((void**)&hwkv, g_wkv);
    cudaGetSymbolAddress((void**)&hwo,  g_wo);

    // fused LN + weight convert
    prepass_k<<<2 * RROWS + 4096, 256>>>(x, ctx, nw, nb, cw, cb, xn, cn,
                                         Wq, Wkv, Wo, hwq, hwkv, hwo);

    cudaFuncSetAttribute(gemm_qkv_k, cudaFuncAttributeMaxDynamicSharedMemorySize, GT_SMEM_BYTES);
    cudaFuncSetAttribute(gemm_o_k,   cudaFuncAttributeMaxDynamicSharedMemorySize, GT_SMEM_BYTES);

    gemm_qkv_k<<<1536, 128, GT_SMEM_BYTES>>>(xn, hwq, qb, cn, hwkv, kvb);

    cudaFuncSetAttribute(attn_k, cudaFuncAttributeMaxDynamicSharedMemorySize, AT_SMEM_BYTES);
    attn_k<<<dim3(NSEQ / 128, BATCH * HEADS), 128, AT_SMEM_BYTES>>>(qb, kvb, mask, ao);

    gemm_o_k<<<512, 128, GT_SMEM_BYTES>>>(ao, hwo, out);
}